// round 10
// baseline (speedup 1.0000x reference)
#include <cuda_runtime.h>
#include <math.h>
#include <stdint.h>

// Problem constants
#define BATCH 2
#define SEQ   2048
#define CH    1024
#define HEADS 16
#define HDIM  64
#define MROWS (BATCH*SEQ)   // 4096
#define NQKV  (3*CH)        // 3072
#define HALF  (HDIM/2)      // 32

// ---------------------------------------------------------------------------
// Device scratch. RULE (round 8): NEVER pass device globals as kernel args
// from host code (host shadow symbol aliases host BSS via ATS on GB300).
// ---------------------------------------------------------------------------
__device__ __align__(16) float g_Q[(size_t)BATCH*HEADS*HDIM*SEQ];  // [b][h][d][s]
__device__ __align__(16) float g_K[(size_t)BATCH*HEADS*HDIM*SEQ];  // [b][h][d][s]
__device__ __align__(16) float g_V[(size_t)BATCH*HEADS*SEQ*HDIM];  // [b][h][s][d]
__device__ __align__(16) float g_AO[(size_t)MROWS*CH];             // attn out f32
__device__ __align__(16) float g_sin[SEQ*HALF];
__device__ __align__(16) float g_cos[SEQ*HALF];

// ---------------------------------------------------------------------------
// Helpers
// ---------------------------------------------------------------------------
__device__ __forceinline__ uint32_t smem_to_u32(const void* p) {
    uint32_t a;
    asm("{ .reg .u64 t; cvta.to.shared.u64 t, %1; cvt.u32.u64 %0, t; }"
        : "=r"(a) : "l"(p));
    return a;
}
__device__ __forceinline__ uint2 lds64(uint32_t a) {
    uint2 v;
    asm volatile("ld.shared.v2.b32 {%0,%1}, [%2];" : "=r"(v.x), "=r"(v.y) : "r"(a));
    return v;
}
__device__ __forceinline__ void sts128(uint32_t a, uint32_t x, uint32_t y,
                                       uint32_t z, uint32_t w) {
    asm volatile("st.shared.v4.b32 [%0], {%1,%2,%3,%4};"
                 :: "r"(a), "r"(x), "r"(y), "r"(z), "r"(w));
}
__device__ __forceinline__ uint32_t f2tf32(float f) {
    uint32_t u;
    asm("cvt.rna.tf32.f32 %0, %1;" : "=r"(u) : "f"(f));
    return u;
}
#define MMA_TF32(c,a0,a1,a2,a3,b0,b1) \
    asm volatile("mma.sync.aligned.m16n8k8.row.col.f32.tf32.tf32.f32 " \
        "{%0,%1,%2,%3}, {%4,%5,%6,%7}, {%8,%9}, {%0,%1,%2,%3};" \
        : "+f"((c)[0]),"+f"((c)[1]),"+f"((c)[2]),"+f"((c)[3]) \
        : "r"(a0),"r"(a1),"r"(a2),"r"(a3), "r"(b0),"r"(b1))

// ---------------------------------------------------------------------------
// RoPE table
// ---------------------------------------------------------------------------
__global__ void rope_table_kernel() {
    int idx = blockIdx.x * blockDim.x + threadIdx.x;
    if (idx < SEQ * HALF) {
        int s = idx >> 5;
        int p = idx & 31;
        float dim_t = powf(10000.0f, (float)p / (float)HALF);
        float ang = (float)s / dim_t;
        g_sin[idx] = sinf(ang);
        g_cos[idx] = cosf(ang);
    }
}

// ---------------------------------------------------------------------------
// TF32 split-2 3-term MMA GEMM v2: C[M,N] = A[M,K] . B[K,N], fp32 in/out.
// vs round-9 verified core: (1) double-buffered smem (ONE barrier/chunk),
// (2) interleaved (hi,lo) 8B pairs -> ld.shared.v2 fragment loads (48 vs 96),
// (3) conflict-free padding for 8B granularity (row offsets step 32B mod 128).
// Fragment map and epilogue are byte-identical logic to the verified round-9.
// CTA 128x128, K-chunk 16, 8 warps (64x32 warp tiles). K = CH.
// MODE 0: A = g_AO (device symbol), plain store. MODE 1: fused QKV epilogue.
// ---------------------------------------------------------------------------
#define AR2 160                       // A row: 16 elem x 8B + 32B pad
#define BR2 1056                      // B row: 128 elem x 8B + 32B pad
#define AT2 (128*AR2)                 // 20480 B
#define BT2 (16*BR2)                  // 16896 B
#define STG (AT2+BT2)                 // 37376 B per stage
#define SMEM_TOT (2*STG)              // 74752 B
#define TFNCHUNK (CH/16)              // 64

template <int MODE>
__global__ __launch_bounds__(256)
void gemm_tf32(const float* __restrict__ A, const float* __restrict__ Bm,
               float* __restrict__ Cout,
               const float* __restrict__ qb, const float* __restrict__ vb,
               int N)
{
    extern __shared__ __align__(16) char sm[];
    const uint32_t smb = smem_to_u32(sm);

    const int tid  = threadIdx.x;
    const int lane = tid & 31;
    const int wid  = tid >> 5;
    const int warpM = wid & 1;
    const int warpN = wid >> 1;
    const int mBlock = blockIdx.y * 128;
    const int nBlock = blockIdx.x * 128;
    const int g = lane >> 2;
    const int t = lane & 3;

    const float* Abase = (MODE == 0) ? (const float*)g_AO : A;

    // loader indices (same global pattern as verified round-9)
    const int arow = tid >> 1;            // 0..127 (m)
    const int ahalf = tid & 1;            // 8 k-elems each
    const int brow = tid >> 4;            // 0..15 (k within chunk)
    const int bseg = tid & 15;            // 8 n-elems each
    const float* gA = Abase + (size_t)(mBlock + arow) * CH + ahalf * 8;
    const float* gB = Bm + (size_t)brow * N + nBlock + bseg * 8;
    const uint32_t sAfill = smb + (uint32_t)(arow * AR2 + ahalf * 64);
    const uint32_t sBfill = smb + AT2 + (uint32_t)(brow * BR2 + bseg * 64);

    float acc[4][4][4];
    #pragma unroll
    for (int i = 0; i < 4; i++)
        #pragma unroll
        for (int j = 0; j < 4; j++)
            #pragma unroll
            for (int k = 0; k < 4; k++) acc[i][j][k] = 0.0f;

    float a8[8], b8[8];
    #pragma unroll
    for (int q = 0; q < 2; q++) {
        *(float4*)&a8[q * 4] = *(const float4*)(gA + q * 4);
        *(float4*)&b8[q * 4] = *(const float4*)(gB + q * 4);
    }
    // convert + store chunk0 -> stage 0
    #pragma unroll
    for (int q = 0; q < 8; q += 2) {
        uint32_t ah0 = f2tf32(a8[q]),     al0 = f2tf32(a8[q]     - __uint_as_float(ah0));
        uint32_t ah1 = f2tf32(a8[q + 1]), al1 = f2tf32(a8[q + 1] - __uint_as_float(ah1));
        sts128(sAfill + q * 8, ah0, al0, ah1, al1);
        uint32_t bh0 = f2tf32(b8[q]),     bl0 = f2tf32(b8[q]     - __uint_as_float(bh0));
        uint32_t bh1 = f2tf32(b8[q + 1]), bl1 = f2tf32(b8[q + 1] - __uint_as_float(bh1));
        sts128(sBfill + q * 8, bh0, bl0, bh1, bl1);
    }
    __syncthreads();

    for (int ck = 0; ck < TFNCHUNK; ck++) {
        const uint32_t stg = (uint32_t)(ck & 1) * STG;

        // global prefetch of next chunk (hidden under mma)
        if (ck + 1 < TFNCHUNK) {
            #pragma unroll
            for (int q = 0; q < 2; q++) {
                *(float4*)&a8[q * 4] = *(const float4*)(gA + (ck + 1) * 16 + q * 4);
                *(float4*)&b8[q * 4] = *(const float4*)(gB + (size_t)(ck + 1) * 16 * N + q * 4);
            }
        }

        // ---- mma on current stage ----
        #pragma unroll
        for (int ks = 0; ks < 2; ks++) {
            uint2 b0[4], b1[4];
            #pragma unroll
            for (int nf = 0; nf < 4; nf++) {
                const uint32_t bb = smb + stg + AT2
                    + (uint32_t)((ks * 8 + t) * BR2 + (warpN * 32 + nf * 8 + g) * 8);
                b0[nf] = lds64(bb);
                b1[nf] = lds64(bb + 4 * BR2);
            }
            #pragma unroll
            for (int mf = 0; mf < 4; mf++) {
                const uint32_t ab = smb + stg
                    + (uint32_t)((warpM * 64 + mf * 16 + g) * AR2 + (ks * 8 + t) * 8);
                uint2 a0 = lds64(ab);
                uint2 a1 = lds64(ab + 8 * AR2);
                uint2 a2 = lds64(ab + 32);
                uint2 a3 = lds64(ab + 8 * AR2 + 32);
                #pragma unroll
                for (int nf = 0; nf < 4; nf++) {
                    MMA_TF32(acc[mf][nf], a0.x, a1.x, a2.x, a3.x, b0[nf].x, b1[nf].x);
                    MMA_TF32(acc[mf][nf], a0.x, a1.x, a2.x, a3.x, b0[nf].y, b1[nf].y);
                    MMA_TF32(acc[mf][nf], a0.y, a1.y, a2.y, a3.y, b0[nf].x, b1[nf].x);
                }
            }
        }

        // convert + store prefetched chunk into the OTHER stage
        // (its last readers were mma at ck-1, separated by the barrier below)
        if (ck + 1 < TFNCHUNK) {
            const uint32_t stg2 = (uint32_t)((ck + 1) & 1) * STG;
            #pragma unroll
            for (int q = 0; q < 8; q += 2) {
                uint32_t ah0 = f2tf32(a8[q]),     al0 = f2tf32(a8[q]     - __uint_as_float(ah0));
                uint32_t ah1 = f2tf32(a8[q + 1]), al1 = f2tf32(a8[q + 1] - __uint_as_float(ah1));
                sts128(sAfill + stg2 + q * 8, ah0, al0, ah1, al1);
                uint32_t bh0 = f2tf32(b8[q]),     bl0 = f2tf32(b8[q]     - __uint_as_float(bh0));
                uint32_t bh1 = f2tf32(b8[q + 1]), bl1 = f2tf32(b8[q + 1] - __uint_as_float(bh1));
                sts128(sBfill + stg2 + q * 8, bh0, bl0, bh1, bl1);
            }
        }
        __syncthreads();
    }

    // ---------------- epilogue (verified round-8/9 logic) ----------------
    const int mrow = mBlock + warpM * 64 + g;
    const int ncol = nBlock + warpN * 32 + t * 2;

    #pragma unroll
    for (int mf = 0; mf < 4; mf++) {
        const int m = mrow + mf * 16;
        #pragma unroll
        for (int nf = 0; nf < 4; nf++) {
            const int n = ncol + nf * 8;
            float* c = acc[mf][nf];
            if (MODE == 0) {
                *(float2*)(Cout + (size_t)m * N + n)       = make_float2(c[0], c[1]);
                *(float2*)(Cout + (size_t)(m + 8) * N + n) = make_float2(c[2], c[3]);
            } else {
                const int sec = n >> 10;            // 0=q 1=k 2=v
                const int c0i = n & (CH - 1);
                const int h   = c0i >> 6;
                const int d   = c0i & 63;           // even
                const int bIdx = m >> 11;
                const int s    = m & (SEQ - 1);
                const size_t bh = (size_t)(bIdx * HEADS + h);
                if (sec == 2) {
                    const float v0 = vb[c0i], v1 = vb[c0i + 1];
                    float* dst = g_V + (bh * SEQ + (size_t)s) * HDIM + d;
                    *(float2*)dst = make_float2(c[0] + v0, c[1] + v1);
                    *(float2*)(dst + 8 * HDIM) = make_float2(c[2] + v0, c[3] + v1);
                } else {
                    float v0 = c[0], v1 = c[1], v2 = c[2], v3 = c[3];
                    if (sec == 0) {
                        const float q0 = qb[c0i], q1 = qb[c0i + 1];
                        v0 += q0; v1 += q1; v2 += q0; v3 += q1;
                    }
                    const int p = d >> 1;
                    const float sn0 = g_sin[s * HALF + p],       cs0 = g_cos[s * HALF + p];
                    const float sn8 = g_sin[(s + 8) * HALF + p], cs8 = g_cos[(s + 8) * HALF + p];
                    float o0 = v0 * cs0 - v1 * sn0;
                    float o1 = v1 * cs0 + v0 * sn0;
                    float o2 = v2 * cs8 - v3 * sn8;
                    float o3 = v3 * cs8 + v2 * sn8;
                    if (sec == 0) { o0 *= 0.125f; o1 *= 0.125f; o2 *= 0.125f; o3 *= 0.125f; }
                    float* base = (sec == 0 ? g_Q : g_K) + bh * (size_t)(HDIM * SEQ);
                    base[(size_t)d * SEQ + s]           = o0;
                    base[(size_t)(d + 1) * SEQ + s]     = o1;
                    base[(size_t)d * SEQ + s + 8]       = o2;
                    base[(size_t)(d + 1) * SEQ + s + 8] = o3;
                }
            }
        }
    }
}

// ---------------------------------------------------------------------------
// Round-1 proven flash attention (fp32, 64x64 tiles, causal) -> g_AO
// ---------------------------------------------------------------------------
__global__ __launch_bounds__(256)
void flash_kernel()
{
    __shared__ float Qs[64 * 64];
    __shared__ float KPs[64 * 64];
    __shared__ float Vs[64 * 64];

    const int tid = threadIdx.x;
    const int tx = tid & 15;
    const int ty = tid >> 4;
    const int bh = blockIdx.y;
    const int qt = (gridDim.x - 1) - blockIdx.x;
    const int q0 = qt * 64;

    const float* Qb = g_Q + (size_t)bh * HDIM * SEQ;
    const float* Kb = g_K + (size_t)bh * HDIM * SEQ;
    const float* Vb = g_V + (size_t)bh * SEQ * HDIM;

    #pragma unroll
    for (int slot = tid; slot < 1024; slot += 256) {
        int d = slot >> 4, r4 = (slot & 15) << 2;
        *(float4*)&Qs[d * 64 + r4] = *(const float4*)&Qb[(size_t)d * SEQ + q0 + r4];
    }

    float m_i[4], l_i[4], o[4][4];
    #pragma unroll
    for (int i = 0; i < 4; i++) {
        m_i[i] = -1e30f;
        l_i[i] = 0.0f;
        #pragma unroll
        for (int j = 0; j < 4; j++) o[i][j] = 0.0f;
    }
    __syncthreads();

    for (int kt = 0; kt <= qt; kt++) {
        const int k0 = kt * 64;
        #pragma unroll
        for (int slot = tid; slot < 1024; slot += 256) {
            int d = slot >> 4, c4 = (slot & 15) << 2;
            *(float4*)&KPs[d * 64 + c4] = *(const float4*)&Kb[(size_t)d * SEQ + k0 + c4];
            *(float4*)&Vs[d * 64 + c4]  = *(const float4*)&Vb[(size_t)(k0 + d) * HDIM + c4];
        }
        __syncthreads();

        float sacc[4][4];
        #pragma unroll
        for (int i = 0; i < 4; i++)
            #pragma unroll
            for (int j = 0; j < 4; j++) sacc[i][j] = 0.0f;

        #pragma unroll 8
        for (int d = 0; d < 64; d++) {
            float q4[4], k4[4];
            *(float4*)q4 = *(const float4*)&Qs[d * 64 + ty * 4];
            *(float4*)k4 = *(const float4*)&KPs[d * 64 + tx * 4];
            #pragma unroll
            for (int i = 0; i < 4; i++)
                #pragma unroll
                for (int j = 0; j < 4; j++)
                    sacc[i][j] = fmaf(q4[i], k4[j], sacc[i][j]);
        }

        if (kt == qt) {
            #pragma unroll
            for (int i = 0; i < 4; i++)
                #pragma unroll
                for (int j = 0; j < 4; j++)
                    if (tx * 4 + j > ty * 4 + i) sacc[i][j] = -1e30f;
        }

        #pragma unroll
        for (int i = 0; i < 4; i++) {
            float mx = fmaxf(fmaxf(sacc[i][0], sacc[i][1]), fmaxf(sacc[i][2], sacc[i][3]));
            #pragma unroll
            for (int ofs = 1; ofs < 16; ofs <<= 1)
                mx = fmaxf(mx, __shfl_xor_sync(0xffffffffu, mx, ofs));
            float mn = fmaxf(m_i[i], mx);
            float al = __expf(m_i[i] - mn);
            float sum = 0.0f;
            #pragma unroll
            for (int j = 0; j < 4; j++) {
                float p = __expf(sacc[i][j] - mn);
                sacc[i][j] = p;
                sum += p;
            }
            #pragma unroll
            for (int ofs = 1; ofs < 16; ofs <<= 1)
                sum += __shfl_xor_sync(0xffffffffu, sum, ofs);
            l_i[i] = l_i[i] * al + sum;
            m_i[i] = mn;
            #pragma unroll
            for (int j = 0; j < 4; j++) o[i][j] *= al;
        }

        __syncthreads();
        #pragma unroll
        for (int j = 0; j < 4; j++) {
            int c = tx * 4 + j;
            int base = c * 64 + ((ty ^ (c & 15)) << 2);
            #pragma unroll
            for (int i = 0; i < 4; i++) KPs[base + i] = sacc[i][j];
        }
        __syncthreads();

        #pragma unroll 8
        for (int k = 0; k < 64; k++) {
            float p4[4], v4[4];
            *(float4*)p4 = *(const float4*)&KPs[k * 64 + ((ty ^ (k & 15)) << 2)];
            *(float4*)v4 = *(const float4*)&Vs[k * 64 + tx * 4];
            #pragma unroll
            for (int i = 0; i < 4; i++)
                #pragma unroll
                for (int j = 0; j < 4; j++)
                    o[i][j] = fmaf(p4[i], v4[j], o[i][j]);
        }
        __syncthreads();
    }

    const int b = bh >> 4;
    const int h = bh & 15;
    #pragma unroll
    for (int i = 0; i < 4; i++) {
        float inv = 1.0f / l_i[i];
        int s = q0 + ty * 4 + i;
        float4 r = make_float4(o[i][0] * inv, o[i][1] * inv,
                               o[i][2] * inv, o[i][3] * inv);
        *(float4*)&g_AO[(size_t)(b * SEQ + s) * CH + h * 64 + tx * 4] = r;
    }
}

// ---------------------------------------------------------------------------
extern "C" void kernel_launch(void* const* d_in, const int* in_sizes, int n_in,
                              void* d_out, int out_size)
{
    const float* x      = (const float*)d_in[0];
    const float* w_qkv  = (const float*)d_in[1];
    const float* q_bias = (const float*)d_in[2];
    const float* v_bias = (const float*)d_in[3];
    const float* w_out  = (const float*)d_in[4];
    float* out = (float*)d_out;

    cudaFuncSetAttribute(gemm_tf32<1>,
                         cudaFuncAttributeMaxDynamicSharedMemorySize, SMEM_TOT);
    cudaFuncSetAttribute(gemm_tf32<0>,
                         cudaFuncAttributeMaxDynamicSharedMemorySize, SMEM_TOT);

    rope_table_kernel<<<SEQ * HALF / 256, 256>>>();

    // QKV projection (tf32 3-term v2) + fused bias/RoPE/scale/scatter
    gemm_tf32<1><<<dim3(NQKV / 128, MROWS / 128), 256, SMEM_TOT>>>(
        x, w_qkv, nullptr, q_bias, v_bias, NQKV);

    // causal flash attention -> g_AO
    flash_kernel<<<dim3(SEQ / 64, BATCH * HEADS), 256>>>();

    // output projection (tf32 3-term v2; A = g_AO selected in device code)
    gemm_tf32<0><<<dim3(CH / 128, MROWS / 128), 256, SMEM_TOT>>>(
        nullptr, w_out, out, nullptr, nullptr, CH);
}

// round 11
// speedup vs baseline: 1.0688x; 1.0688x over previous
#include <cuda_runtime.h>
#include <math.h>
#include <stdint.h>

// Problem constants
#define BATCH 2
#define SEQ   2048
#define CH    1024
#define HEADS 16
#define HDIM  64
#define MROWS (BATCH*SEQ)   // 4096
#define NQKV  (3*CH)        // 3072
#define HALF  (HDIM/2)      // 32

// ---------------------------------------------------------------------------
// Device scratch. RULE (round 8): NEVER pass device globals as kernel args
// from host code (host shadow symbol aliases host BSS via ATS on GB300).
// ---------------------------------------------------------------------------
__device__ __align__(16) float g_Q[(size_t)BATCH*HEADS*HDIM*SEQ];  // [b][h][d][s]
__device__ __align__(16) float g_K[(size_t)BATCH*HEADS*HDIM*SEQ];  // [b][h][d][s]
__device__ __align__(16) float g_V[(size_t)BATCH*HEADS*SEQ*HDIM];  // [b][h][s][d]
__device__ __align__(16) float g_AO[(size_t)MROWS*CH];             // attn out f32
__device__ __align__(16) float g_sin[SEQ*HALF];
__device__ __align__(16) float g_cos[SEQ*HALF];

// ---------------------------------------------------------------------------
// Helpers
// ---------------------------------------------------------------------------
__device__ __forceinline__ uint32_t smem_to_u32(const void* p) {
    uint32_t a;
    asm("{ .reg .u64 t; cvta.to.shared.u64 t, %1; cvt.u32.u64 %0, t; }"
        : "=r"(a) : "l"(p));
    return a;
}
__device__ __forceinline__ uint2 lds64(uint32_t a) {
    uint2 v;
    asm volatile("ld.shared.v2.b32 {%0,%1}, [%2];" : "=r"(v.x), "=r"(v.y) : "r"(a));
    return v;
}
__device__ __forceinline__ void sts128(uint32_t a, uint32_t x, uint32_t y,
                                       uint32_t z, uint32_t w) {
    asm volatile("st.shared.v4.b32 [%0], {%1,%2,%3,%4};"
                 :: "r"(a), "r"(x), "r"(y), "r"(z), "r"(w));
}
__device__ __forceinline__ uint32_t f2tf32(float f) {
    uint32_t u;
    asm("cvt.rna.tf32.f32 %0, %1;" : "=r"(u) : "f"(f));
    return u;
}
#define MMA_TF32(c,a0,a1,a2,a3,b0,b1) \
    asm volatile("mma.sync.aligned.m16n8k8.row.col.f32.tf32.tf32.f32 " \
        "{%0,%1,%2,%3}, {%4,%5,%6,%7}, {%8,%9}, {%0,%1,%2,%3};" \
        : "+f"((c)[0]),"+f"((c)[1]),"+f"((c)[2]),"+f"((c)[3]) \
        : "r"(a0),"r"(a1),"r"(a2),"r"(a3), "r"(b0),"r"(b1))

// ---------------------------------------------------------------------------
// RoPE table
// ---------------------------------------------------------------------------
__global__ void rope_table_kernel() {
    int idx = blockIdx.x * blockDim.x + threadIdx.x;
    if (idx < SEQ * HALF) {
        int s = idx >> 5;
        int p = idx & 31;
        float dim_t = powf(10000.0f, (float)p / (float)HALF);
        float ang = (float)s / dim_t;
        g_sin[idx] = sinf(ang);
        g_cos[idx] = cosf(ang);
    }
}

// ---------------------------------------------------------------------------
// TF32 split-2 3-term MMA GEMM v3: C[M,N] = A[M,K] . B[K,N], fp32 in/out.
// vs v2: 512 threads / 16 warps per CTA (4x4 warp grid, 32x32 warp tiles)
// -> 4 warps/SMSP to hide mma latency; ~32 acc regs/thread.
// Double-buffered smem, interleaved (hi,lo) 8B pairs, ld.shared.v2 frags.
// CTA 128x128, K-chunk 16, K = CH = 1024.
// MODE 0: A = g_AO (device symbol), plain store. MODE 1: fused QKV epilogue.
// ---------------------------------------------------------------------------
#define AR2 160                       // A row: 16 elem x 8B + 32B pad
#define BR2 1056                      // B row: 128 elem x 8B + 32B pad
#define AT2 (128*AR2)                 // 20480 B
#define BT2 (16*BR2)                  // 16896 B
#define STG (AT2+BT2)                 // 37376 B per stage
#define SMEM_TOT (2*STG)              // 74752 B
#define TFNCHUNK (CH/16)              // 64
#define NTHREADS 512

template <int MODE>
__global__ __launch_bounds__(NTHREADS, 1)
void gemm_tf32(const float* __restrict__ A, const float* __restrict__ Bm,
               float* __restrict__ Cout,
               const float* __restrict__ qb, const float* __restrict__ vb,
               int N)
{
    extern __shared__ __align__(16) char sm[];
    const uint32_t smb = smem_to_u32(sm);

    const int tid  = threadIdx.x;
    const int lane = tid & 31;
    const int wid  = tid >> 5;          // 0..15
    const int warpM = wid & 3;          // 4 x 32 rows
    const int warpN = wid >> 2;         // 4 x 32 cols
    const int mBlock = blockIdx.y * 128;
    const int nBlock = blockIdx.x * 128;
    const int g = lane >> 2;
    const int t = lane & 3;

    const float* Abase = (MODE == 0) ? (const float*)g_AO : A;

    // loaders: each thread moves one float4 of A and one of B per chunk
    const int arow = tid >> 2;            // 0..127 (m)
    const int aq   = tid & 3;             // 4 k-elems each
    const int brow = tid >> 5;            // 0..15 (k within chunk)
    const int bseg = tid & 31;            // 4 n-elems each
    const float* gA = Abase + (size_t)(mBlock + arow) * CH + aq * 4;
    const float* gB = Bm + (size_t)brow * N + nBlock + bseg * 4;
    const uint32_t sAfill = smb + (uint32_t)(arow * AR2 + aq * 32);
    const uint32_t sBfill = smb + AT2 + (uint32_t)(brow * BR2 + bseg * 32);

    float acc[2][4][4];
    #pragma unroll
    for (int i = 0; i < 2; i++)
        #pragma unroll
        for (int j = 0; j < 4; j++)
            #pragma unroll
            for (int k = 0; k < 4; k++) acc[i][j][k] = 0.0f;

    float4 a4, b4;
    a4 = *(const float4*)(gA);
    b4 = *(const float4*)(gB);

    // convert + store chunk0 -> stage 0
    {
        uint32_t h0 = f2tf32(a4.x), l0 = f2tf32(a4.x - __uint_as_float(h0));
        uint32_t h1 = f2tf32(a4.y), l1 = f2tf32(a4.y - __uint_as_float(h1));
        sts128(sAfill, h0, l0, h1, l1);
        uint32_t h2 = f2tf32(a4.z), l2 = f2tf32(a4.z - __uint_as_float(h2));
        uint32_t h3 = f2tf32(a4.w), l3 = f2tf32(a4.w - __uint_as_float(h3));
        sts128(sAfill + 16, h2, l2, h3, l3);
        h0 = f2tf32(b4.x); l0 = f2tf32(b4.x - __uint_as_float(h0));
        h1 = f2tf32(b4.y); l1 = f2tf32(b4.y - __uint_as_float(h1));
        sts128(sBfill, h0, l0, h1, l1);
        h2 = f2tf32(b4.z); l2 = f2tf32(b4.z - __uint_as_float(h2));
        h3 = f2tf32(b4.w); l3 = f2tf32(b4.w - __uint_as_float(h3));
        sts128(sBfill + 16, h2, l2, h3, l3);
    }
    __syncthreads();

    for (int ck = 0; ck < TFNCHUNK; ck++) {
        const uint32_t stg = (uint32_t)(ck & 1) * STG;

        // global prefetch of next chunk (hidden under mma)
        if (ck + 1 < TFNCHUNK) {
            a4 = *(const float4*)(gA + (ck + 1) * 16);
            b4 = *(const float4*)(gB + (size_t)(ck + 1) * 16 * N);
        }

        // ---- mma on current stage ----
        #pragma unroll
        for (int ks = 0; ks < 2; ks++) {
            uint2 b0[4], b1[4];
            #pragma unroll
            for (int nf = 0; nf < 4; nf++) {
                const uint32_t bb = smb + stg + AT2
                    + (uint32_t)((ks * 8 + t) * BR2 + (warpN * 32 + nf * 8 + g) * 8);
                b0[nf] = lds64(bb);
                b1[nf] = lds64(bb + 4 * BR2);
            }
            #pragma unroll
            for (int mf = 0; mf < 2; mf++) {
                const uint32_t ab = smb + stg
                    + (uint32_t)((warpM * 32 + mf * 16 + g) * AR2 + (ks * 8 + t) * 8);
                uint2 a0 = lds64(ab);
                uint2 a1 = lds64(ab + 8 * AR2);
                uint2 a2 = lds64(ab + 32);
                uint2 a3 = lds64(ab + 8 * AR2 + 32);
                #pragma unroll
                for (int nf = 0; nf < 4; nf++) {
                    MMA_TF32(acc[mf][nf], a0.x, a1.x, a2.x, a3.x, b0[nf].x, b1[nf].x);
                    MMA_TF32(acc[mf][nf], a0.x, a1.x, a2.x, a3.x, b0[nf].y, b1[nf].y);
                    MMA_TF32(acc[mf][nf], a0.y, a1.y, a2.y, a3.y, b0[nf].x, b1[nf].x);
                }
            }
        }

        // convert + store prefetched chunk into the OTHER stage
        if (ck + 1 < TFNCHUNK) {
            const uint32_t stg2 = (uint32_t)((ck + 1) & 1) * STG;
            uint32_t h0 = f2tf32(a4.x), l0 = f2tf32(a4.x - __uint_as_float(h0));
            uint32_t h1 = f2tf32(a4.y), l1 = f2tf32(a4.y - __uint_as_float(h1));
            sts128(sAfill + stg2, h0, l0, h1, l1);
            uint32_t h2 = f2tf32(a4.z), l2 = f2tf32(a4.z - __uint_as_float(h2));
            uint32_t h3 = f2tf32(a4.w), l3 = f2tf32(a4.w - __uint_as_float(h3));
            sts128(sAfill + stg2 + 16, h2, l2, h3, l3);
            h0 = f2tf32(b4.x); l0 = f2tf32(b4.x - __uint_as_float(h0));
            h1 = f2tf32(b4.y); l1 = f2tf32(b4.y - __uint_as_float(h1));
            sts128(sBfill + stg2, h0, l0, h1, l1);
            h2 = f2tf32(b4.z); l2 = f2tf32(b4.z - __uint_as_float(h2));
            h3 = f2tf32(b4.w); l3 = f2tf32(b4.w - __uint_as_float(h3));
            sts128(sBfill + stg2 + 16, h2, l2, h3, l3);
        }
        __syncthreads();
    }

    // ---------------- epilogue (verified round-8/9 logic) ----------------
    const int mrow = mBlock + warpM * 32 + g;
    const int ncol = nBlock + warpN * 32 + t * 2;

    #pragma unroll
    for (int mf = 0; mf < 2; mf++) {
        const int m = mrow + mf * 16;
        #pragma unroll
        for (int nf = 0; nf < 4; nf++) {
            const int n = ncol + nf * 8;
            float* c = acc[mf][nf];
            if (MODE == 0) {
                *(float2*)(Cout + (size_t)m * N + n)       = make_float2(c[0], c[1]);
                *(float2*)(Cout + (size_t)(m + 8) * N + n) = make_float2(c[2], c[3]);
            } else {
                const int sec = n >> 10;            // 0=q 1=k 2=v
                const int c0i = n & (CH - 1);
                const int h   = c0i >> 6;
                const int d   = c0i & 63;           // even
                const int bIdx = m >> 11;
                const int s    = m & (SEQ - 1);
                const size_t bh = (size_t)(bIdx * HEADS + h);
                if (sec == 2) {
                    const float v0 = vb[c0i], v1 = vb[c0i + 1];
                    float* dst = g_V + (bh * SEQ + (size_t)s) * HDIM + d;
                    *(float2*)dst = make_float2(c[0] + v0, c[1] + v1);
                    *(float2*)(dst + 8 * HDIM) = make_float2(c[2] + v0, c[3] + v1);
                } else {
                    float v0 = c[0], v1 = c[1], v2 = c[2], v3 = c[3];
                    if (sec == 0) {
                        const float q0 = qb[c0i], q1 = qb[c0i + 1];
                        v0 += q0; v1 += q1; v2 += q0; v3 += q1;
                    }
                    const int p = d >> 1;
                    const float sn0 = g_sin[s * HALF + p],       cs0 = g_cos[s * HALF + p];
                    const float sn8 = g_sin[(s + 8) * HALF + p], cs8 = g_cos[(s + 8) * HALF + p];
                    float o0 = v0 * cs0 - v1 * sn0;
                    float o1 = v1 * cs0 + v0 * sn0;
                    float o2 = v2 * cs8 - v3 * sn8;
                    float o3 = v3 * cs8 + v2 * sn8;
                    if (sec == 0) { o0 *= 0.125f; o1 *= 0.125f; o2 *= 0.125f; o3 *= 0.125f; }
                    float* base = (sec == 0 ? g_Q : g_K) + bh * (size_t)(HDIM * SEQ);
                    base[(size_t)d * SEQ + s]           = o0;
                    base[(size_t)(d + 1) * SEQ + s]     = o1;
                    base[(size_t)d * SEQ + s + 8]       = o2;
                    base[(size_t)(d + 1) * SEQ + s + 8] = o3;
                }
            }
        }
    }
}

// ---------------------------------------------------------------------------
// Round-1 proven flash attention (fp32, 64x64 tiles, causal) -> g_AO
// ---------------------------------------------------------------------------
__global__ __launch_bounds__(256)
void flash_kernel()
{
    __shared__ float Qs[64 * 64];
    __shared__ float KPs[64 * 64];
    __shared__ float Vs[64 * 64];

    const int tid = threadIdx.x;
    const int tx = tid & 15;
    const int ty = tid >> 4;
    const int bh = blockIdx.y;
    const int qt = (gridDim.x - 1) - blockIdx.x;
    const int q0 = qt * 64;

    const float* Qb = g_Q + (size_t)bh * HDIM * SEQ;
    const float* Kb = g_K + (size_t)bh * HDIM * SEQ;
    const float* Vb = g_V + (size_t)bh * SEQ * HDIM;

    #pragma unroll
    for (int slot = tid; slot < 1024; slot += 256) {
        int d = slot >> 4, r4 = (slot & 15) << 2;
        *(float4*)&Qs[d * 64 + r4] = *(const float4*)&Qb[(size_t)d * SEQ + q0 + r4];
    }

    float m_i[4], l_i[4], o[4][4];
    #pragma unroll
    for (int i = 0; i < 4; i++) {
        m_i[i] = -1e30f;
        l_i[i] = 0.0f;
        #pragma unroll
        for (int j = 0; j < 4; j++) o[i][j] = 0.0f;
    }
    __syncthreads();

    for (int kt = 0; kt <= qt; kt++) {
        const int k0 = kt * 64;
        #pragma unroll
        for (int slot = tid; slot < 1024; slot += 256) {
            int d = slot >> 4, c4 = (slot & 15) << 2;
            *(float4*)&KPs[d * 64 + c4] = *(const float4*)&Kb[(size_t)d * SEQ + k0 + c4];
            *(float4*)&Vs[d * 64 + c4]  = *(const float4*)&Vb[(size_t)(k0 + d) * HDIM + c4];
        }
        __syncthreads();

        float sacc[4][4];
        #pragma unroll
        for (int i = 0; i < 4; i++)
            #pragma unroll
            for (int j = 0; j < 4; j++) sacc[i][j] = 0.0f;

        #pragma unroll 8
        for (int d = 0; d < 64; d++) {
            float q4[4], k4[4];
            *(float4*)q4 = *(const float4*)&Qs[d * 64 + ty * 4];
            *(float4*)k4 = *(const float4*)&KPs[d * 64 + tx * 4];
            #pragma unroll
            for (int i = 0; i < 4; i++)
                #pragma unroll
                for (int j = 0; j < 4; j++)
                    sacc[i][j] = fmaf(q4[i], k4[j], sacc[i][j]);
        }

        if (kt == qt) {
            #pragma unroll
            for (int i = 0; i < 4; i++)
                #pragma unroll
                for (int j = 0; j < 4; j++)
                    if (tx * 4 + j > ty * 4 + i) sacc[i][j] = -1e30f;
        }

        #pragma unroll
        for (int i = 0; i < 4; i++) {
            float mx = fmaxf(fmaxf(sacc[i][0], sacc[i][1]), fmaxf(sacc[i][2], sacc[i][3]));
            #pragma unroll
            for (int ofs = 1; ofs < 16; ofs <<= 1)
                mx = fmaxf(mx, __shfl_xor_sync(0xffffffffu, mx, ofs));
            float mn = fmaxf(m_i[i], mx);
            float al = __expf(m_i[i] - mn);
            float sum = 0.0f;
            #pragma unroll
            for (int j = 0; j < 4; j++) {
                float p = __expf(sacc[i][j] - mn);
                sacc[i][j] = p;
                sum += p;
            }
            #pragma unroll
            for (int ofs = 1; ofs < 16; ofs <<= 1)
                sum += __shfl_xor_sync(0xffffffffu, sum, ofs);
            l_i[i] = l_i[i] * al + sum;
            m_i[i] = mn;
            #pragma unroll
            for (int j = 0; j < 4; j++) o[i][j] *= al;
        }

        __syncthreads();
        #pragma unroll
        for (int j = 0; j < 4; j++) {
            int c = tx * 4 + j;
            int base = c * 64 + ((ty ^ (c & 15)) << 2);
            #pragma unroll
            for (int i = 0; i < 4; i++) KPs[base + i] = sacc[i][j];
        }
        __syncthreads();

        #pragma unroll 8
        for (int k = 0; k < 64; k++) {
            float p4[4], v4[4];
            *(float4*)p4 = *(const float4*)&KPs[k * 64 + ((ty ^ (k & 15)) << 2)];
            *(float4*)v4 = *(const float4*)&Vs[k * 64 + tx * 4];
            #pragma unroll
            for (int i = 0; i < 4; i++)
                #pragma unroll
                for (int j = 0; j < 4; j++)
                    o[i][j] = fmaf(p4[i], v4[j], o[i][j]);
        }
        __syncthreads();
    }

    const int b = bh >> 4;
    const int h = bh & 15;
    #pragma unroll
    for (int i = 0; i < 4; i++) {
        float inv = 1.0f / l_i[i];
        int s = q0 + ty * 4 + i;
        float4 r = make_float4(o[i][0] * inv, o[i][1] * inv,
                               o[i][2] * inv, o[i][3] * inv);
        *(float4*)&g_AO[(size_t)(b * SEQ + s) * CH + h * 64 + tx * 4] = r;
    }
}

// ---------------------------------------------------------------------------
extern "C" void kernel_launch(void* const* d_in, const int* in_sizes, int n_in,
                              void* d_out, int out_size)
{
    const float* x      = (const float*)d_in[0];
    const float* w_qkv  = (const float*)d_in[1];
    const float* q_bias = (const float*)d_in[2];
    const float* v_bias = (const float*)d_in[3];
    const float* w_out  = (const float*)d_in[4];
    float* out = (float*)d_out;

    cudaFuncSetAttribute(gemm_tf32<1>,
                         cudaFuncAttributeMaxDynamicSharedMemorySize, SMEM_TOT);
    cudaFuncSetAttribute(gemm_tf32<0>,
                         cudaFuncAttributeMaxDynamicSharedMemorySize, SMEM_TOT);

    rope_table_kernel<<<SEQ * HALF / 256, 256>>>();

    // QKV projection (tf32 3-term v3, 16 warps) + fused bias/RoPE/scale/scatter
    gemm_tf32<1><<<dim3(NQKV / 128, MROWS / 128), NTHREADS, SMEM_TOT>>>(
        x, w_qkv, nullptr, q_bias, v_bias, NQKV);

    // causal flash attention -> g_AO
    flash_kernel<<<dim3(SEQ / 64, BATCH * HEADS), 256>>>();

    // output projection (tf32 3-term v3; A = g_AO selected in device code)
    gemm_tf32<0><<<dim3(CH / 128, MROWS / 128), NTHREADS, SMEM_TOT>>>(
        nullptr, w_out, out, nullptr, nullptr, CH);
}

// round 12
// speedup vs baseline: 1.0712x; 1.0022x over previous
#include <cuda_runtime.h>
#include <math.h>
#include <stdint.h>

// Problem constants
#define BATCH 2
#define SEQ   2048
#define CH    1024
#define HEADS 16
#define HDIM  64
#define MROWS (BATCH*SEQ)   // 4096
#define NQKV  (3*CH)        // 3072
#define HALF  (HDIM/2)      // 32

// ---------------------------------------------------------------------------
// Device scratch. RULE (round 8): NEVER pass device globals as kernel args
// from host code (host shadow symbol aliases host BSS via ATS on GB300).
// ---------------------------------------------------------------------------
__device__ __align__(16) float g_Q[(size_t)BATCH*HEADS*HDIM*SEQ];  // [b][h][d][s]
__device__ __align__(16) float g_K[(size_t)BATCH*HEADS*HDIM*SEQ];  // [b][h][d][s]
__device__ __align__(16) float g_V[(size_t)BATCH*HEADS*SEQ*HDIM];  // [b][h][s][d]
__device__ __align__(16) float g_AO[(size_t)MROWS*CH];             // attn out f32
__device__ __align__(16) float g_sin[SEQ*HALF];
__device__ __align__(16) float g_cos[SEQ*HALF];

// ---------------------------------------------------------------------------
// Helpers
// ---------------------------------------------------------------------------
__device__ __forceinline__ uint32_t smem_to_u32(const void* p) {
    uint32_t a;
    asm("{ .reg .u64 t; cvta.to.shared.u64 t, %1; cvt.u32.u64 %0, t; }"
        : "=r"(a) : "l"(p));
    return a;
}
__device__ __forceinline__ uint2 lds64(uint32_t a) {
    uint2 v;
    asm volatile("ld.shared.v2.b32 {%0,%1}, [%2];" : "=r"(v.x), "=r"(v.y) : "r"(a));
    return v;
}
__device__ __forceinline__ void sts128(uint32_t a, uint32_t x, uint32_t y,
                                       uint32_t z, uint32_t w) {
    asm volatile("st.shared.v4.b32 [%0], {%1,%2,%3,%4};"
                 :: "r"(a), "r"(x), "r"(y), "r"(z), "r"(w));
}
__device__ __forceinline__ uint32_t f2tf32(float f) {
    uint32_t u;
    asm("cvt.rna.tf32.f32 %0, %1;" : "=r"(u) : "f"(f));
    return u;
}
#define MMA_TF32(c,a0,a1,a2,a3,b0,b1) \
    asm volatile("mma.sync.aligned.m16n8k8.row.col.f32.tf32.tf32.f32 " \
        "{%0,%1,%2,%3}, {%4,%5,%6,%7}, {%8,%9}, {%0,%1,%2,%3};" \
        : "+f"((c)[0]),"+f"((c)[1]),"+f"((c)[2]),"+f"((c)[3]) \
        : "r"(a0),"r"(a1),"r"(a2),"r"(a3), "r"(b0),"r"(b1))

// ---------------------------------------------------------------------------
// RoPE table
// ---------------------------------------------------------------------------
__global__ void rope_table_kernel() {
    int idx = blockIdx.x * blockDim.x + threadIdx.x;
    if (idx < SEQ * HALF) {
        int s = idx >> 5;
        int p = idx & 31;
        float dim_t = powf(10000.0f, (float)p / (float)HALF);
        float ang = (float)s / dim_t;
        g_sin[idx] = sinf(ang);
        g_cos[idx] = cosf(ang);
    }
}

// ---------------------------------------------------------------------------
// TF32 split-2 3-term MMA GEMM v4: C[M,N] = A[M,K] . B[K,N], fp32 in/out.
// vs v3: chunk loop manually unrolled x2 so stage offsets are compile-time;
// per-warp fragment bases hoisted -> inner loop is pure [reg+imm] lds/mma.
// 512 threads / 16 warps, 32x32 warp tiles, double-buffered interleaved smem.
// MODE 0: A = g_AO (device symbol), plain store. MODE 1: fused QKV epilogue.
// ---------------------------------------------------------------------------
#define AR2 160                       // A row: 16 elem x 8B + 32B pad
#define BR2 1056                      // B row: 128 elem x 8B + 32B pad
#define AT2 (128*AR2)                 // 20480 B
#define BT2 (16*BR2)                  // 16896 B
#define STG (AT2+BT2)                 // 37376 B per stage
#define SMEM_TOT (2*STG)              // 74752 B
#define TFNCHUNK (CH/16)              // 64
#define NTHREADS 512

// mma over one stage; SOFF is a compile-time stage byte offset.
template <int SOFF>
__device__ __forceinline__ void mma_stage(uint32_t aBase, uint32_t bBase,
                                          float (&acc)[2][4][4])
{
    #pragma unroll
    for (int ks = 0; ks < 2; ks++) {
        uint2 b0[4], b1[4];
        #pragma unroll
        for (int nf = 0; nf < 4; nf++) {
            b0[nf] = lds64(bBase + SOFF + ks * 8 * BR2 + nf * 64);
            b1[nf] = lds64(bBase + SOFF + ks * 8 * BR2 + 4 * BR2 + nf * 64);
        }
        #pragma unroll
        for (int mf = 0; mf < 2; mf++) {
            const uint32_t ab = aBase + SOFF + mf * 16 * AR2 + ks * 64;
            uint2 a0 = lds64(ab);
            uint2 a1 = lds64(ab + 8 * AR2);
            uint2 a2 = lds64(ab + 32);
            uint2 a3 = lds64(ab + 8 * AR2 + 32);
            #pragma unroll
            for (int nf = 0; nf < 4; nf++) {
                MMA_TF32(acc[mf][nf], a0.x, a1.x, a2.x, a3.x, b0[nf].x, b1[nf].x);
                MMA_TF32(acc[mf][nf], a0.x, a1.x, a2.x, a3.x, b0[nf].y, b1[nf].y);
                MMA_TF32(acc[mf][nf], a0.y, a1.y, a2.y, a3.y, b0[nf].x, b1[nf].x);
            }
        }
    }
}

// convert + store one (A-float4, B-float4) into stage SOFF.
template <int SOFF>
__device__ __forceinline__ void cvt_store(uint32_t sAfill, uint32_t sBfill,
                                          float4 a4, float4 b4)
{
    uint32_t h0 = f2tf32(a4.x), l0 = f2tf32(a4.x - __uint_as_float(h0));
    uint32_t h1 = f2tf32(a4.y), l1 = f2tf32(a4.y - __uint_as_float(h1));
    sts128(sAfill + SOFF, h0, l0, h1, l1);
    uint32_t h2 = f2tf32(a4.z), l2 = f2tf32(a4.z - __uint_as_float(h2));
    uint32_t h3 = f2tf32(a4.w), l3 = f2tf32(a4.w - __uint_as_float(h3));
    sts128(sAfill + SOFF + 16, h2, l2, h3, l3);
    h0 = f2tf32(b4.x); l0 = f2tf32(b4.x - __uint_as_float(h0));
    h1 = f2tf32(b4.y); l1 = f2tf32(b4.y - __uint_as_float(h1));
    sts128(sBfill + SOFF, h0, l0, h1, l1);
    h2 = f2tf32(b4.z); l2 = f2tf32(b4.z - __uint_as_float(h2));
    h3 = f2tf32(b4.w); l3 = f2tf32(b4.w - __uint_as_float(h3));
    sts128(sBfill + SOFF + 16, h2, l2, h3, l3);
}

template <int MODE>
__global__ __launch_bounds__(NTHREADS, 1)
void gemm_tf32(const float* __restrict__ A, const float* __restrict__ Bm,
               float* __restrict__ Cout,
               const float* __restrict__ qb, const float* __restrict__ vb,
               int N)
{
    extern __shared__ __align__(16) char sm[];
    const uint32_t smb = smem_to_u32(sm);

    const int tid  = threadIdx.x;
    const int lane = tid & 31;
    const int wid  = tid >> 5;          // 0..15
    const int warpM = wid & 3;          // 4 x 32 rows
    const int warpN = wid >> 2;         // 4 x 32 cols
    const int mBlock = blockIdx.y * 128;
    const int nBlock = blockIdx.x * 128;
    const int g = lane >> 2;
    const int t = lane & 3;

    const float* Abase = (MODE == 0) ? (const float*)g_AO : A;

    // loaders: one float4 of A and one of B per thread per chunk
    const int arow = tid >> 2;            // 0..127 (m)
    const int aq   = tid & 3;             // 4 k-elems each
    const int brow = tid >> 5;            // 0..15 (k within chunk)
    const int bseg = tid & 31;            // 4 n-elems each
    const float* gA = Abase + (size_t)(mBlock + arow) * CH + aq * 4;
    const float* gB = Bm + (size_t)brow * N + nBlock + bseg * 4;
    const uint32_t sAfill = smb + (uint32_t)(arow * AR2 + aq * 32);
    const uint32_t sBfill = smb + AT2 + (uint32_t)(brow * BR2 + bseg * 32);

    // hoisted per-warp fragment bases (loop-invariant)
    const uint32_t aBase = smb + (uint32_t)((warpM * 32 + g) * AR2 + t * 8);
    const uint32_t bBase = smb + AT2 + (uint32_t)(t * BR2 + (warpN * 32 + g) * 8);

    float acc[2][4][4];
    #pragma unroll
    for (int i = 0; i < 2; i++)
        #pragma unroll
        for (int j = 0; j < 4; j++)
            #pragma unroll
            for (int k = 0; k < 4; k++) acc[i][j][k] = 0.0f;

    float4 a4 = *(const float4*)(gA);
    float4 b4 = *(const float4*)(gB);
    cvt_store<0>(sAfill, sBfill, a4, b4);
    __syncthreads();

    const size_t bstride16 = (size_t)16 * N;

    #pragma unroll 1
    for (int ck = 0; ck < TFNCHUNK; ck += 2) {
        // ---- even chunk (stage 0) ----
        a4 = *(const float4*)(gA + (ck + 1) * 16);            // prefetch ck+1
        b4 = *(const float4*)(gB + (size_t)(ck + 1) * bstride16);
        mma_stage<0>(aBase, bBase, acc);
        cvt_store<STG>(sAfill, sBfill, a4, b4);
        __syncthreads();

        // ---- odd chunk (stage 1) ----
        if (ck + 2 < TFNCHUNK) {
            a4 = *(const float4*)(gA + (ck + 2) * 16);        // prefetch ck+2
            b4 = *(const float4*)(gB + (size_t)(ck + 2) * bstride16);
        }
        mma_stage<STG>(aBase, bBase, acc);
        if (ck + 2 < TFNCHUNK) {
            cvt_store<0>(sAfill, sBfill, a4, b4);
        }
        __syncthreads();
    }

    // ---------------- epilogue (verified round-8/9 logic) ----------------
    const int mrow = mBlock + warpM * 32 + g;
    const int ncol = nBlock + warpN * 32 + t * 2;

    #pragma unroll
    for (int mf = 0; mf < 2; mf++) {
        const int m = mrow + mf * 16;
        #pragma unroll
        for (int nf = 0; nf < 4; nf++) {
            const int n = ncol + nf * 8;
            float* c = acc[mf][nf];
            if (MODE == 0) {
                *(float2*)(Cout + (size_t)m * N + n)       = make_float2(c[0], c[1]);
                *(float2*)(Cout + (size_t)(m + 8) * N + n) = make_float2(c[2], c[3]);
            } else {
                const int sec = n >> 10;            // 0=q 1=k 2=v
                const int c0i = n & (CH - 1);
                const int h   = c0i >> 6;
                const int d   = c0i & 63;           // even
                const int bIdx = m >> 11;
                const int s    = m & (SEQ - 1);
                const size_t bh = (size_t)(bIdx * HEADS + h);
                if (sec == 2) {
                    const float v0 = vb[c0i], v1 = vb[c0i + 1];
                    float* dst = g_V + (bh * SEQ + (size_t)s) * HDIM + d;
                    *(float2*)dst = make_float2(c[0] + v0, c[1] + v1);
                    *(float2*)(dst + 8 * HDIM) = make_float2(c[2] + v0, c[3] + v1);
                } else {
                    float v0 = c[0], v1 = c[1], v2 = c[2], v3 = c[3];
                    if (sec == 0) {
                        const float q0 = qb[c0i], q1 = qb[c0i + 1];
                        v0 += q0; v1 += q1; v2 += q0; v3 += q1;
                    }
                    const int p = d >> 1;
                    const float sn0 = g_sin[s * HALF + p],       cs0 = g_cos[s * HALF + p];
                    const float sn8 = g_sin[(s + 8) * HALF + p], cs8 = g_cos[(s + 8) * HALF + p];
                    float o0 = v0 * cs0 - v1 * sn0;
                    float o1 = v1 * cs0 + v0 * sn0;
                    float o2 = v2 * cs8 - v3 * sn8;
                    float o3 = v3 * cs8 + v2 * sn8;
                    if (sec == 0) { o0 *= 0.125f; o1 *= 0.125f; o2 *= 0.125f; o3 *= 0.125f; }
                    float* base = (sec == 0 ? g_Q : g_K) + bh * (size_t)(HDIM * SEQ);
                    base[(size_t)d * SEQ + s]           = o0;
                    base[(size_t)(d + 1) * SEQ + s]     = o1;
                    base[(size_t)d * SEQ + s + 8]       = o2;
                    base[(size_t)(d + 1) * SEQ + s + 8] = o3;
                }
            }
        }
    }
}

// ---------------------------------------------------------------------------
// Round-1 proven flash attention (fp32, 64x64 tiles, causal) -> g_AO
// ---------------------------------------------------------------------------
__global__ __launch_bounds__(256)
void flash_kernel()
{
    __shared__ float Qs[64 * 64];
    __shared__ float KPs[64 * 64];
    __shared__ float Vs[64 * 64];

    const int tid = threadIdx.x;
    const int tx = tid & 15;
    const int ty = tid >> 4;
    const int bh = blockIdx.y;
    const int qt = (gridDim.x - 1) - blockIdx.x;
    const int q0 = qt * 64;

    const float* Qb = g_Q + (size_t)bh * HDIM * SEQ;
    const float* Kb = g_K + (size_t)bh * HDIM * SEQ;
    const float* Vb = g_V + (size_t)bh * SEQ * HDIM;

    #pragma unroll
    for (int slot = tid; slot < 1024; slot += 256) {
        int d = slot >> 4, r4 = (slot & 15) << 2;
        *(float4*)&Qs[d * 64 + r4] = *(const float4*)&Qb[(size_t)d * SEQ + q0 + r4];
    }

    float m_i[4], l_i[4], o[4][4];
    #pragma unroll
    for (int i = 0; i < 4; i++) {
        m_i[i] = -1e30f;
        l_i[i] = 0.0f;
        #pragma unroll
        for (int j = 0; j < 4; j++) o[i][j] = 0.0f;
    }
    __syncthreads();

    for (int kt = 0; kt <= qt; kt++) {
        const int k0 = kt * 64;
        #pragma unroll
        for (int slot = tid; slot < 1024; slot += 256) {
            int d = slot >> 4, c4 = (slot & 15) << 2;
            *(float4*)&KPs[d * 64 + c4] = *(const float4*)&Kb[(size_t)d * SEQ + k0 + c4];
            *(float4*)&Vs[d * 64 + c4]  = *(const float4*)&Vb[(size_t)(k0 + d) * HDIM + c4];
        }
        __syncthreads();

        float sacc[4][4];
        #pragma unroll
        for (int i = 0; i < 4; i++)
            #pragma unroll
            for (int j = 0; j < 4; j++) sacc[i][j] = 0.0f;

        #pragma unroll 8
        for (int d = 0; d < 64; d++) {
            float q4[4], k4[4];
            *(float4*)q4 = *(const float4*)&Qs[d * 64 + ty * 4];
            *(float4*)k4 = *(const float4*)&KPs[d * 64 + tx * 4];
            #pragma unroll
            for (int i = 0; i < 4; i++)
                #pragma unroll
                for (int j = 0; j < 4; j++)
                    sacc[i][j] = fmaf(q4[i], k4[j], sacc[i][j]);
        }

        if (kt == qt) {
            #pragma unroll
            for (int i = 0; i < 4; i++)
                #pragma unroll
                for (int j = 0; j < 4; j++)
                    if (tx * 4 + j > ty * 4 + i) sacc[i][j] = -1e30f;
        }

        #pragma unroll
        for (int i = 0; i < 4; i++) {
            float mx = fmaxf(fmaxf(sacc[i][0], sacc[i][1]), fmaxf(sacc[i][2], sacc[i][3]));
            #pragma unroll
            for (int ofs = 1; ofs < 16; ofs <<= 1)
                mx = fmaxf(mx, __shfl_xor_sync(0xffffffffu, mx, ofs));
            float mn = fmaxf(m_i[i], mx);
            float al = __expf(m_i[i] - mn);
            float sum = 0.0f;
            #pragma unroll
            for (int j = 0; j < 4; j++) {
                float p = __expf(sacc[i][j] - mn);
                sacc[i][j] = p;
                sum += p;
            }
            #pragma unroll
            for (int ofs = 1; ofs < 16; ofs <<= 1)
                sum += __shfl_xor_sync(0xffffffffu, sum, ofs);
            l_i[i] = l_i[i] * al + sum;
            m_i[i] = mn;
            #pragma unroll
            for (int j = 0; j < 4; j++) o[i][j] *= al;
        }

        __syncthreads();
        #pragma unroll
        for (int j = 0; j < 4; j++) {
            int c = tx * 4 + j;
            int base = c * 64 + ((ty ^ (c & 15)) << 2);
            #pragma unroll
            for (int i = 0; i < 4; i++) KPs[base + i] = sacc[i][j];
        }
        __syncthreads();

        #pragma unroll 8
        for (int k = 0; k < 64; k++) {
            float p4[4], v4[4];
            *(float4*)p4 = *(const float4*)&KPs[k * 64 + ((ty ^ (k & 15)) << 2)];
            *(float4*)v4 = *(const float4*)&Vs[k * 64 + tx * 4];
            #pragma unroll
            for (int i = 0; i < 4; i++)
                #pragma unroll
                for (int j = 0; j < 4; j++)
                    o[i][j] = fmaf(p4[i], v4[j], o[i][j]);
        }
        __syncthreads();
    }

    const int b = bh >> 4;
    const int h = bh & 15;
    #pragma unroll
    for (int i = 0; i < 4; i++) {
        float inv = 1.0f / l_i[i];
        int s = q0 + ty * 4 + i;
        float4 r = make_float4(o[i][0] * inv, o[i][1] * inv,
                               o[i][2] * inv, o[i][3] * inv);
        *(float4*)&g_AO[(size_t)(b * SEQ + s) * CH + h * 64 + tx * 4] = r;
    }
}

// ---------------------------------------------------------------------------
extern "C" void kernel_launch(void* const* d_in, const int* in_sizes, int n_in,
                              void* d_out, int out_size)
{
    const float* x      = (const float*)d_in[0];
    const float* w_qkv  = (const float*)d_in[1];
    const float* q_bias = (const float*)d_in[2];
    const float* v_bias = (const float*)d_in[3];
    const float* w_out  = (const float*)d_in[4];
    float* out = (float*)d_out;

    cudaFuncSetAttribute(gemm_tf32<1>,
                         cudaFuncAttributeMaxDynamicSharedMemorySize, SMEM_TOT);
    cudaFuncSetAttribute(gemm_tf32<0>,
                         cudaFuncAttributeMaxDynamicSharedMemorySize, SMEM_TOT);

    rope_table_kernel<<<SEQ * HALF / 256, 256>>>();

    // QKV projection (tf32 3-term v4) + fused bias/RoPE/scale/scatter
    gemm_tf32<1><<<dim3(NQKV / 128, MROWS / 128), NTHREADS, SMEM_TOT>>>(
        x, w_qkv, nullptr, q_bias, v_bias, NQKV);

    // causal flash attention -> g_AO
    flash_kernel<<<dim3(SEQ / 64, BATCH * HEADS), 256>>>();

    // output projection (tf32 3-term v4; A = g_AO selected in device code)
    gemm_tf32<0><<<dim3(CH / 128, MROWS / 128), NTHREADS, SMEM_TOT>>>(
        nullptr, w_out, out, nullptr, nullptr, CH);
}

// round 13
// speedup vs baseline: 1.4121x; 1.3183x over previous
#include <cuda_runtime.h>
#include <cuda_fp16.h>
#include <math.h>
#include <stdint.h>

// Problem constants
#define BATCH 2
#define SEQ   2048
#define CH    1024
#define HEADS 16
#define HDIM  64
#define MROWS (BATCH*SEQ)   // 4096
#define NQKV  (3*CH)        // 3072
#define HALF  (HDIM/2)      // 32

// ---------------------------------------------------------------------------
// Device scratch. RULE (round 8): NEVER pass device globals as kernel args
// from host code (host shadow symbol aliases host BSS via ATS on GB300).
// ---------------------------------------------------------------------------
__device__ __align__(16) float g_Q[(size_t)BATCH*HEADS*HDIM*SEQ];  // [b][h][d][s]
__device__ __align__(16) float g_K[(size_t)BATCH*HEADS*HDIM*SEQ];  // [b][h][d][s]
__device__ __align__(16) float g_V[(size_t)BATCH*HEADS*SEQ*HDIM];  // [b][h][s][d]
__device__ __align__(16) float g_AO[(size_t)MROWS*CH];             // attn out f32
__device__ __align__(16) float g_sin[SEQ*HALF];
__device__ __align__(16) float g_cos[SEQ*HALF];

// ---------------------------------------------------------------------------
// Helpers
// ---------------------------------------------------------------------------
__device__ __forceinline__ uint32_t smem_to_u32(const void* p) {
    uint32_t a;
    asm("{ .reg .u64 t; cvta.to.shared.u64 t, %1; cvt.u32.u64 %0, t; }"
        : "=r"(a) : "l"(p));
    return a;
}
__device__ __forceinline__ uint2 lds64(uint32_t a) {
    uint2 v;
    asm volatile("ld.shared.v2.b32 {%0,%1}, [%2];" : "=r"(v.x), "=r"(v.y) : "r"(a));
    return v;
}
__device__ __forceinline__ void sts128(uint32_t a, uint32_t x, uint32_t y,
                                       uint32_t z, uint32_t w) {
    asm volatile("st.shared.v4.b32 [%0], {%1,%2,%3,%4};"
                 :: "r"(a), "r"(x), "r"(y), "r"(z), "r"(w));
}
// split two floats into packed fp16 (hi-pair, lo-pair)
__device__ __forceinline__ void cvt_pair(float x, float y,
                                         uint32_t& hi, uint32_t& lo) {
    __half hx = __float2half_rn(x), hy = __float2half_rn(y);
    float rx = x - __half2float(hx), ry = y - __half2float(hy);
    __half lx = __float2half_rn(rx), ly = __float2half_rn(ry);
    hi = (uint32_t)__half_as_ushort(hx) | ((uint32_t)__half_as_ushort(hy) << 16);
    lo = (uint32_t)__half_as_ushort(lx) | ((uint32_t)__half_as_ushort(ly) << 16);
}
#define MMA_F16(c,a0,a1,a2,a3,b0,b1) \
    asm volatile("mma.sync.aligned.m16n8k16.row.col.f32.f16.f16.f32 " \
        "{%0,%1,%2,%3}, {%4,%5,%6,%7}, {%8,%9}, {%0,%1,%2,%3};" \
        : "+f"((c)[0]),"+f"((c)[1]),"+f"((c)[2]),"+f"((c)[3]) \
        : "r"(a0),"r"(a1),"r"(a2),"r"(a3), "r"(b0),"r"(b1))

// ---------------------------------------------------------------------------
// RoPE table
// ---------------------------------------------------------------------------
__global__ void rope_table_kernel() {
    int idx = blockIdx.x * blockDim.x + threadIdx.x;
    if (idx < SEQ * HALF) {
        int s = idx >> 5;
        int p = idx & 31;
        float dim_t = powf(10000.0f, (float)p / (float)HALF);
        float ang = (float)s / dim_t;
        g_sin[idx] = sinf(ang);
        g_cos[idx] = cosf(ang);
    }
}

// ---------------------------------------------------------------------------
// FP16 split-2 3-term MMA GEMM v5 (m16n8k16): C[M,N] = A[M,K].B[K,N], fp32 IO.
// Same verified v4 byte geometry; entries are 8B (hi-pair, lo-pair) half2
// packed along k. K-chunk 32 (2 k16 steps). 512 threads, 16 warps, 32x32
// warp tiles, double-buffered smem.
// MODE 0: A = g_AO (device symbol), plain store. MODE 1: fused QKV epilogue.
// ---------------------------------------------------------------------------
#define AR2 160                       // A row: 16 k2-entries x 8B + 32B pad
#define BR2 1056                      // B row: 128 n-entries x 8B + 32B pad
#define AT2 (128*AR2)                 // 20480 B
#define BT2 (16*BR2)                  // 16896 B (16 k2-rows per chunk of 32 k)
#define STG (AT2+BT2)                 // 37376 B per stage
#define SMEM_TOT (2*STG)              // 74752 B
#define NCH32 (CH/32)                 // 32 chunks
#define NTHREADS 512

// mma over one stage; SOFF compile-time stage byte offset.
template <int SOFF>
__device__ __forceinline__ void mma_stage(uint32_t aBase, uint32_t bBase,
                                          float (&acc)[2][4][4])
{
    #pragma unroll
    for (int ks = 0; ks < 2; ks++) {
        uint2 b0[4], b1[4];
        #pragma unroll
        for (int nf = 0; nf < 4; nf++) {
            b0[nf] = lds64(bBase + SOFF + ks * 8 * BR2 + nf * 64);
            b1[nf] = lds64(bBase + SOFF + ks * 8 * BR2 + 4 * BR2 + nf * 64);
        }
        #pragma unroll
        for (int mf = 0; mf < 2; mf++) {
            const uint32_t ab = aBase + SOFF + mf * 16 * AR2 + ks * 64;
            uint2 a0 = lds64(ab);
            uint2 a1 = lds64(ab + 8 * AR2);
            uint2 a2 = lds64(ab + 32);
            uint2 a3 = lds64(ab + 8 * AR2 + 32);
            #pragma unroll
            for (int nf = 0; nf < 4; nf++) {
                MMA_F16(acc[mf][nf], a0.x, a1.x, a2.x, a3.x, b0[nf].x, b1[nf].x);
                MMA_F16(acc[mf][nf], a0.x, a1.x, a2.x, a3.x, b0[nf].y, b1[nf].y);
                MMA_F16(acc[mf][nf], a0.y, a1.y, a2.y, a3.y, b0[nf].x, b1[nf].x);
            }
        }
    }
}

// convert + store one chunk's worth (A: 2 float4; B: 4 float2 spanning k pairs)
template <int SOFF>
__device__ __forceinline__ void cvt_store(uint32_t sAfill, uint32_t sBfill,
                                          float4 aa, float4 ab,
                                          float2 b0, float2 b1,
                                          float2 b2, float2 b3)
{
    uint32_t h0, l0, h1, l1;
    // A: k2 entries 2q, 2q+1 (k = 4q..4q+3)
    cvt_pair(aa.x, aa.y, h0, l0); cvt_pair(aa.z, aa.w, h1, l1);
    sts128(sAfill + SOFF, h0, l0, h1, l1);
    // A: k = 16+4q
    cvt_pair(ab.x, ab.y, h0, l0); cvt_pair(ab.z, ab.w, h1, l1);
    sts128(sAfill + SOFF + 64, h0, l0, h1, l1);
    // B row kk: n = 2n2 from (b0.x,b1.x), n = 2n2+1 from (b0.y,b1.y)
    cvt_pair(b0.x, b1.x, h0, l0); cvt_pair(b0.y, b1.y, h1, l1);
    sts128(sBfill + SOFF, h0, l0, h1, l1);
    // B row kk+8 (k = +16)
    cvt_pair(b2.x, b3.x, h0, l0); cvt_pair(b2.y, b3.y, h1, l1);
    sts128(sBfill + SOFF + 8 * BR2, h0, l0, h1, l1);
}

template <int MODE>
__global__ __launch_bounds__(NTHREADS, 1)
void gemm_f16(const float* __restrict__ A, const float* __restrict__ Bm,
              float* __restrict__ Cout,
              const float* __restrict__ qb, const float* __restrict__ vb,
              int N)
{
    extern __shared__ __align__(16) char sm[];
    const uint32_t smb = smem_to_u32(sm);

    const int tid  = threadIdx.x;
    const int lane = tid & 31;
    const int wid  = tid >> 5;          // 0..15
    const int warpM = wid & 3;          // 4 x 32 rows
    const int warpN = wid >> 2;         // 4 x 32 cols
    const int mBlock = blockIdx.y * 128;
    const int nBlock = blockIdx.x * 128;
    const int g = lane >> 2;
    const int t = lane & 3;

    const float* Abase = (MODE == 0) ? (const float*)g_AO : A;

    // A loader: float4 at (arow, 4q) and (arow, 16+4q)
    const int arow = tid >> 2;            // 0..127 (m)
    const int aq   = tid & 3;
    const float* gA = Abase + (size_t)(mBlock + arow) * CH + aq * 4;
    const uint32_t sAfill = smb + (uint32_t)(arow * AR2 + aq * 16);

    // B loader: k2-row kk (k rows 2kk,2kk+1) and kk+8; n pair 2n2
    const int kk = tid >> 6;              // 0..7
    const int n2 = tid & 63;
    const float* gB = Bm + (size_t)(2 * kk) * N + nBlock + 2 * n2;
    const uint32_t sBfill = smb + AT2 + (uint32_t)(kk * BR2 + n2 * 16);

    // hoisted per-warp fragment bases
    const uint32_t aBase = smb + (uint32_t)((warpM * 32 + g) * AR2 + t * 8);
    const uint32_t bBase = smb + AT2 + (uint32_t)(t * BR2 + (warpN * 32 + g) * 8);

    float acc[2][4][4];
    #pragma unroll
    for (int i = 0; i < 2; i++)
        #pragma unroll
        for (int j = 0; j < 4; j++)
            #pragma unroll
            for (int k = 0; k < 4; k++) acc[i][j][k] = 0.0f;

    const size_t bN = (size_t)N;

    float4 aa = *(const float4*)(gA);
    float4 ab = *(const float4*)(gA + 16);
    float2 b0 = *(const float2*)(gB);
    float2 b1 = *(const float2*)(gB + bN);
    float2 b2 = *(const float2*)(gB + 16 * bN);
    float2 b3 = *(const float2*)(gB + 17 * bN);
    cvt_store<0>(sAfill, sBfill, aa, ab, b0, b1, b2, b3);
    __syncthreads();

    #pragma unroll 1
    for (int ck = 0; ck < NCH32; ck += 2) {
        // prefetch chunk ck+1
        {
            const int ko = (ck + 1) * 32;
            aa = *(const float4*)(gA + ko);
            ab = *(const float4*)(gA + ko + 16);
            const float* gb = gB + (size_t)ko * bN;
            b0 = *(const float2*)(gb);
            b1 = *(const float2*)(gb + bN);
            b2 = *(const float2*)(gb + 16 * bN);
            b3 = *(const float2*)(gb + 17 * bN);
        }
        mma_stage<0>(aBase, bBase, acc);
        cvt_store<STG>(sAfill, sBfill, aa, ab, b0, b1, b2, b3);
        __syncthreads();

        if (ck + 2 < NCH32) {
            const int ko = (ck + 2) * 32;
            aa = *(const float4*)(gA + ko);
            ab = *(const float4*)(gA + ko + 16);
            const float* gb = gB + (size_t)ko * bN;
            b0 = *(const float2*)(gb);
            b1 = *(const float2*)(gb + bN);
            b2 = *(const float2*)(gb + 16 * bN);
            b3 = *(const float2*)(gb + 17 * bN);
        }
        mma_stage<STG>(aBase, bBase, acc);
        if (ck + 2 < NCH32) {
            cvt_store<0>(sAfill, sBfill, aa, ab, b0, b1, b2, b3);
        }
        __syncthreads();
    }

    // ---------------- epilogue (verified round-8/9 logic) ----------------
    const int mrow = mBlock + warpM * 32 + g;
    const int ncol = nBlock + warpN * 32 + t * 2;

    #pragma unroll
    for (int mf = 0; mf < 2; mf++) {
        const int m = mrow + mf * 16;
        #pragma unroll
        for (int nf = 0; nf < 4; nf++) {
            const int n = ncol + nf * 8;
            float* c = acc[mf][nf];
            if (MODE == 0) {
                *(float2*)(Cout + (size_t)m * N + n)       = make_float2(c[0], c[1]);
                *(float2*)(Cout + (size_t)(m + 8) * N + n) = make_float2(c[2], c[3]);
            } else {
                const int sec = n >> 10;            // 0=q 1=k 2=v
                const int c0i = n & (CH - 1);
                const int h   = c0i >> 6;
                const int d   = c0i & 63;           // even
                const int bIdx = m >> 11;
                const int s    = m & (SEQ - 1);
                const size_t bh = (size_t)(bIdx * HEADS + h);
                if (sec == 2) {
                    const float v0 = vb[c0i], v1 = vb[c0i + 1];
                    float* dst = g_V + (bh * SEQ + (size_t)s) * HDIM + d;
                    *(float2*)dst = make_float2(c[0] + v0, c[1] + v1);
                    *(float2*)(dst + 8 * HDIM) = make_float2(c[2] + v0, c[3] + v1);
                } else {
                    float v0 = c[0], v1 = c[1], v2 = c[2], v3 = c[3];
                    if (sec == 0) {
                        const float q0 = qb[c0i], q1 = qb[c0i + 1];
                        v0 += q0; v1 += q1; v2 += q0; v3 += q1;
                    }
                    const int p = d >> 1;
                    const float sn0 = g_sin[s * HALF + p],       cs0 = g_cos[s * HALF + p];
                    const float sn8 = g_sin[(s + 8) * HALF + p], cs8 = g_cos[(s + 8) * HALF + p];
                    float o0 = v0 * cs0 - v1 * sn0;
                    float o1 = v1 * cs0 + v0 * sn0;
                    float o2 = v2 * cs8 - v3 * sn8;
                    float o3 = v3 * cs8 + v2 * sn8;
                    if (sec == 0) { o0 *= 0.125f; o1 *= 0.125f; o2 *= 0.125f; o3 *= 0.125f; }
                    float* base = (sec == 0 ? g_Q : g_K) + bh * (size_t)(HDIM * SEQ);
                    base[(size_t)d * SEQ + s]           = o0;
                    base[(size_t)(d + 1) * SEQ + s]     = o1;
                    base[(size_t)d * SEQ + s + 8]       = o2;
                    base[(size_t)(d + 1) * SEQ + s + 8] = o3;
                }
            }
        }
    }
}

// ---------------------------------------------------------------------------
// Round-1 proven flash attention (fp32, 64x64 tiles, causal) -> g_AO
// ---------------------------------------------------------------------------
__global__ __launch_bounds__(256)
void flash_kernel()
{
    __shared__ float Qs[64 * 64];
    __shared__ float KPs[64 * 64];
    __shared__ float Vs[64 * 64];

    const int tid = threadIdx.x;
    const int tx = tid & 15;
    const int ty = tid >> 4;
    const int bh = blockIdx.y;
    const int qt = (gridDim.x - 1) - blockIdx.x;
    const int q0 = qt * 64;

    const float* Qb = g_Q + (size_t)bh * HDIM * SEQ;
    const float* Kb = g_K + (size_t)bh * HDIM * SEQ;
    const float* Vb = g_V + (size_t)bh * SEQ * HDIM;

    #pragma unroll
    for (int slot = tid; slot < 1024; slot += 256) {
        int d = slot >> 4, r4 = (slot & 15) << 2;
        *(float4*)&Qs[d * 64 + r4] = *(const float4*)&Qb[(size_t)d * SEQ + q0 + r4];
    }

    float m_i[4], l_i[4], o[4][4];
    #pragma unroll
    for (int i = 0; i < 4; i++) {
        m_i[i] = -1e30f;
        l_i[i] = 0.0f;
        #pragma unroll
        for (int j = 0; j < 4; j++) o[i][j] = 0.0f;
    }
    __syncthreads();

    for (int kt = 0; kt <= qt; kt++) {
        const int k0 = kt * 64;
        #pragma unroll
        for (int slot = tid; slot < 1024; slot += 256) {
            int d = slot >> 4, c4 = (slot & 15) << 2;
            *(float4*)&KPs[d * 64 + c4] = *(const float4*)&Kb[(size_t)d * SEQ + k0 + c4];
            *(float4*)&Vs[d * 64 + c4]  = *(const float4*)&Vb[(size_t)(k0 + d) * HDIM + c4];
        }
        __syncthreads();

        float sacc[4][4];
        #pragma unroll
        for (int i = 0; i < 4; i++)
            #pragma unroll
            for (int j = 0; j < 4; j++) sacc[i][j] = 0.0f;

        #pragma unroll 8
        for (int d = 0; d < 64; d++) {
            float q4[4], k4[4];
            *(float4*)q4 = *(const float4*)&Qs[d * 64 + ty * 4];
            *(float4*)k4 = *(const float4*)&KPs[d * 64 + tx * 4];
            #pragma unroll
            for (int i = 0; i < 4; i++)
                #pragma unroll
                for (int j = 0; j < 4; j++)
                    sacc[i][j] = fmaf(q4[i], k4[j], sacc[i][j]);
        }

        if (kt == qt) {
            #pragma unroll
            for (int i = 0; i < 4; i++)
                #pragma unroll
                for (int j = 0; j < 4; j++)
                    if (tx * 4 + j > ty * 4 + i) sacc[i][j] = -1e30f;
        }

        #pragma unroll
        for (int i = 0; i < 4; i++) {
            float mx = fmaxf(fmaxf(sacc[i][0], sacc[i][1]), fmaxf(sacc[i][2], sacc[i][3]));
            #pragma unroll
            for (int ofs = 1; ofs < 16; ofs <<= 1)
                mx = fmaxf(mx, __shfl_xor_sync(0xffffffffu, mx, ofs));
            float mn = fmaxf(m_i[i], mx);
            float al = __expf(m_i[i] - mn);
            float sum = 0.0f;
            #pragma unroll
            for (int j = 0; j < 4; j++) {
                float p = __expf(sacc[i][j] - mn);
                sacc[i][j] = p;
                sum += p;
            }
            #pragma unroll
            for (int ofs = 1; ofs < 16; ofs <<= 1)
                sum += __shfl_xor_sync(0xffffffffu, sum, ofs);
            l_i[i] = l_i[i] * al + sum;
            m_i[i] = mn;
            #pragma unroll
            for (int j = 0; j < 4; j++) o[i][j] *= al;
        }

        __syncthreads();
        #pragma unroll
        for (int j = 0; j < 4; j++) {
            int c = tx * 4 + j;
            int base = c * 64 + ((ty ^ (c & 15)) << 2);
            #pragma unroll
            for (int i = 0; i < 4; i++) KPs[base + i] = sacc[i][j];
        }
        __syncthreads();

        #pragma unroll 8
        for (int k = 0; k < 64; k++) {
            float p4[4], v4[4];
            *(float4*)p4 = *(const float4*)&KPs[k * 64 + ((ty ^ (k & 15)) << 2)];
            *(float4*)v4 = *(const float4*)&Vs[k * 64 + tx * 4];
            #pragma unroll
            for (int i = 0; i < 4; i++)
                #pragma unroll
                for (int j = 0; j < 4; j++)
                    o[i][j] = fmaf(p4[i], v4[j], o[i][j]);
        }
        __syncthreads();
    }

    const int b = bh >> 4;
    const int h = bh & 15;
    #pragma unroll
    for (int i = 0; i < 4; i++) {
        float inv = 1.0f / l_i[i];
        int s = q0 + ty * 4 + i;
        float4 r = make_float4(o[i][0] * inv, o[i][1] * inv,
                               o[i][2] * inv, o[i][3] * inv);
        *(float4*)&g_AO[(size_t)(b * SEQ + s) * CH + h * 64 + tx * 4] = r;
    }
}

// ---------------------------------------------------------------------------
extern "C" void kernel_launch(void* const* d_in, const int* in_sizes, int n_in,
                              void* d_out, int out_size)
{
    const float* x      = (const float*)d_in[0];
    const float* w_qkv  = (const float*)d_in[1];
    const float* q_bias = (const float*)d_in[2];
    const float* v_bias = (const float*)d_in[3];
    const float* w_out  = (const float*)d_in[4];
    float* out = (float*)d_out;

    cudaFuncSetAttribute(gemm_f16<1>,
                         cudaFuncAttributeMaxDynamicSharedMemorySize, SMEM_TOT);
    cudaFuncSetAttribute(gemm_f16<0>,
                         cudaFuncAttributeMaxDynamicSharedMemorySize, SMEM_TOT);

    rope_table_kernel<<<SEQ * HALF / 256, 256>>>();

    // QKV projection (fp16 3-term k16) + fused bias/RoPE/scale/scatter
    gemm_f16<1><<<dim3(NQKV / 128, MROWS / 128), NTHREADS, SMEM_TOT>>>(
        x, w_qkv, nullptr, q_bias, v_bias, NQKV);

    // causal flash attention -> g_AO
    flash_kernel<<<dim3(SEQ / 64, BATCH * HEADS), 256>>>();

    // output projection (fp16 3-term k16; A = g_AO selected in device code)
    gemm_f16<0><<<dim3(CH / 128, MROWS / 128), NTHREADS, SMEM_TOT>>>(
        nullptr, w_out, out, nullptr, nullptr, CH);
}

// round 15
// speedup vs baseline: 1.8191x; 1.2882x over previous
#include <cuda_runtime.h>
#include <cuda_fp16.h>
#include <math.h>
#include <stdint.h>

// Problem constants
#define BATCH 2
#define SEQ   2048
#define CH    1024
#define HEADS 16
#define HDIM  64
#define MROWS (BATCH*SEQ)   // 4096
#define NQKV  (3*CH)        // 3072
#define HALF  (HDIM/2)      // 32

// ---------------------------------------------------------------------------
// Device scratch. RULE (round 8): NEVER pass device globals as kernel args
// from host code (host shadow symbol aliases host BSS via ATS on GB300).
// ---------------------------------------------------------------------------
__device__ __align__(16) float g_V[(size_t)BATCH*HEADS*SEQ*HDIM];  // [bh][s][d] f32
__device__ __align__(16) float g_AO[(size_t)MROWS*CH];             // attn out f32
__device__ __align__(16) uint2 g_Qe[(size_t)BATCH*HEADS*SEQ*32];   // [bh][s][d2] split-fp16
__device__ __align__(16) uint2 g_Ke[(size_t)BATCH*HEADS*32*SEQ];   // [bh][d2][s] split-fp16
__device__ __align__(16) float g_sin[SEQ*HALF];
__device__ __align__(16) float g_cos[SEQ*HALF];

// ---------------------------------------------------------------------------
// Helpers
// ---------------------------------------------------------------------------
__device__ __forceinline__ uint32_t smem_to_u32(const void* p) {
    uint32_t a;
    asm("{ .reg .u64 t; cvta.to.shared.u64 t, %1; cvt.u32.u64 %0, t; }"
        : "=r"(a) : "l"(p));
    return a;
}
__device__ __forceinline__ uint2 lds64(uint32_t a) {
    uint2 v;
    asm volatile("ld.shared.v2.b32 {%0,%1}, [%2];" : "=r"(v.x), "=r"(v.y) : "r"(a));
    return v;
}
__device__ __forceinline__ void sts128(uint32_t a, uint32_t x, uint32_t y,
                                       uint32_t z, uint32_t w) {
    asm volatile("st.shared.v4.b32 [%0], {%1,%2,%3,%4};"
                 :: "r"(a), "r"(x), "r"(y), "r"(z), "r"(w));
}
// split two floats into packed fp16 (hi-pair, lo-pair)
__device__ __forceinline__ void cvt_pair(float x, float y,
                                         uint32_t& hi, uint32_t& lo) {
    __half hx = __float2half_rn(x), hy = __float2half_rn(y);
    float rx = x - __half2float(hx), ry = y - __half2float(hy);
    __half lx = __float2half_rn(rx), ly = __float2half_rn(ry);
    hi = (uint32_t)__half_as_ushort(hx) | ((uint32_t)__half_as_ushort(hy) << 16);
    lo = (uint32_t)__half_as_ushort(lx) | ((uint32_t)__half_as_ushort(ly) << 16);
}
#define MMA_F16(c,a0,a1,a2,a3,b0,b1) \
    asm volatile("mma.sync.aligned.m16n8k16.row.col.f32.f16.f16.f32 " \
        "{%0,%1,%2,%3}, {%4,%5,%6,%7}, {%8,%9}, {%0,%1,%2,%3};" \
        : "+f"((c)[0]),"+f"((c)[1]),"+f"((c)[2]),"+f"((c)[3]) \
        : "r"(a0),"r"(a1),"r"(a2),"r"(a3), "r"(b0),"r"(b1))

// ---------------------------------------------------------------------------
// RoPE table
// ---------------------------------------------------------------------------
__global__ void rope_table_kernel() {
    int idx = blockIdx.x * blockDim.x + threadIdx.x;
    if (idx < SEQ * HALF) {
        int s = idx >> 5;
        int p = idx & 31;
        float dim_t = powf(10000.0f, (float)p / (float)HALF);
        float ang = (float)s / dim_t;
        g_sin[idx] = sinf(ang);
        g_cos[idx] = cosf(ang);
    }
}

// ---------------------------------------------------------------------------
// FP16 split-2 3-term MMA GEMM (round-13 verified core): C = A.B, fp32 IO.
// MODE 0: A = g_AO (device symbol), plain store.
// MODE 1: QKV epilogue -> g_Qe/g_Ke (split-fp16 MMA-ready), g_V (f32).
// ---------------------------------------------------------------------------
#define AR2 160
#define BR2 1056
#define AT2 (128*AR2)
#define BT2 (16*BR2)
#define STG (AT2+BT2)
#define SMEM_TOT (2*STG)
#define NCH32 (CH/32)
#define NTHREADS 512

template <int SOFF>
__device__ __forceinline__ void mma_stage(uint32_t aBase, uint32_t bBase,
                                          float (&acc)[2][4][4])
{
    #pragma unroll
    for (int ks = 0; ks < 2; ks++) {
        uint2 b0[4], b1[4];
        #pragma unroll
        for (int nf = 0; nf < 4; nf++) {
            b0[nf] = lds64(bBase + SOFF + ks * 8 * BR2 + nf * 64);
            b1[nf] = lds64(bBase + SOFF + ks * 8 * BR2 + 4 * BR2 + nf * 64);
        }
        #pragma unroll
        for (int mf = 0; mf < 2; mf++) {
            const uint32_t ab = aBase + SOFF + mf * 16 * AR2 + ks * 64;
            uint2 a0 = lds64(ab);
            uint2 a1 = lds64(ab + 8 * AR2);
            uint2 a2 = lds64(ab + 32);
            uint2 a3 = lds64(ab + 8 * AR2 + 32);
            #pragma unroll
            for (int nf = 0; nf < 4; nf++) {
                MMA_F16(acc[mf][nf], a0.x, a1.x, a2.x, a3.x, b0[nf].x, b1[nf].x);
                MMA_F16(acc[mf][nf], a0.x, a1.x, a2.x, a3.x, b0[nf].y, b1[nf].y);
                MMA_F16(acc[mf][nf], a0.y, a1.y, a2.y, a3.y, b0[nf].x, b1[nf].x);
            }
        }
    }
}

template <int SOFF>
__device__ __forceinline__ void cvt_store(uint32_t sAfill, uint32_t sBfill,
                                          float4 aa, float4 ab,
                                          float2 b0, float2 b1,
                                          float2 b2, float2 b3)
{
    uint32_t h0, l0, h1, l1;
    cvt_pair(aa.x, aa.y, h0, l0); cvt_pair(aa.z, aa.w, h1, l1);
    sts128(sAfill + SOFF, h0, l0, h1, l1);
    cvt_pair(ab.x, ab.y, h0, l0); cvt_pair(ab.z, ab.w, h1, l1);
    sts128(sAfill + SOFF + 64, h0, l0, h1, l1);
    cvt_pair(b0.x, b1.x, h0, l0); cvt_pair(b0.y, b1.y, h1, l1);
    sts128(sBfill + SOFF, h0, l0, h1, l1);
    cvt_pair(b2.x, b3.x, h0, l0); cvt_pair(b2.y, b3.y, h1, l1);
    sts128(sBfill + SOFF + 8 * BR2, h0, l0, h1, l1);
}

template <int MODE>
__global__ __launch_bounds__(NTHREADS, 1)
void gemm_f16(const float* __restrict__ A, const float* __restrict__ Bm,
              float* __restrict__ Cout,
              const float* __restrict__ qb, const float* __restrict__ vb,
              int N)
{
    extern __shared__ __align__(16) char sm[];
    const uint32_t smb = smem_to_u32(sm);

    const int tid  = threadIdx.x;
    const int lane = tid & 31;
    const int wid  = tid >> 5;
    const int warpM = wid & 3;
    const int warpN = wid >> 2;
    const int mBlock = blockIdx.y * 128;
    const int nBlock = blockIdx.x * 128;
    const int g = lane >> 2;
    const int t = lane & 3;

    const float* Abase = (MODE == 0) ? (const float*)g_AO : A;

    const int arow = tid >> 2;
    const int aq   = tid & 3;
    const float* gA = Abase + (size_t)(mBlock + arow) * CH + aq * 4;
    const uint32_t sAfill = smb + (uint32_t)(arow * AR2 + aq * 16);

    const int kk = tid >> 6;
    const int n2 = tid & 63;
    const float* gB = Bm + (size_t)(2 * kk) * N + nBlock + 2 * n2;
    const uint32_t sBfill = smb + AT2 + (uint32_t)(kk * BR2 + n2 * 16);

    const uint32_t aBase = smb + (uint32_t)((warpM * 32 + g) * AR2 + t * 8);
    const uint32_t bBase = smb + AT2 + (uint32_t)(t * BR2 + (warpN * 32 + g) * 8);

    float acc[2][4][4];
    #pragma unroll
    for (int i = 0; i < 2; i++)
        #pragma unroll
        for (int j = 0; j < 4; j++)
            #pragma unroll
            for (int k = 0; k < 4; k++) acc[i][j][k] = 0.0f;

    const size_t bN = (size_t)N;

    float4 aa = *(const float4*)(gA);
    float4 ab = *(const float4*)(gA + 16);
    float2 b0 = *(const float2*)(gB);
    float2 b1 = *(const float2*)(gB + bN);
    float2 b2 = *(const float2*)(gB + 16 * bN);
    float2 b3 = *(const float2*)(gB + 17 * bN);
    cvt_store<0>(sAfill, sBfill, aa, ab, b0, b1, b2, b3);
    __syncthreads();

    #pragma unroll 1
    for (int ck = 0; ck < NCH32; ck += 2) {
        {
            const int ko = (ck + 1) * 32;
            aa = *(const float4*)(gA + ko);
            ab = *(const float4*)(gA + ko + 16);
            const float* gb = gB + (size_t)ko * bN;
            b0 = *(const float2*)(gb);
            b1 = *(const float2*)(gb + bN);
            b2 = *(const float2*)(gb + 16 * bN);
            b3 = *(const float2*)(gb + 17 * bN);
        }
        mma_stage<0>(aBase, bBase, acc);
        cvt_store<STG>(sAfill, sBfill, aa, ab, b0, b1, b2, b3);
        __syncthreads();

        if (ck + 2 < NCH32) {
            const int ko = (ck + 2) * 32;
            aa = *(const float4*)(gA + ko);
            ab = *(const float4*)(gA + ko + 16);
            const float* gb = gB + (size_t)ko * bN;
            b0 = *(const float2*)(gb);
            b1 = *(const float2*)(gb + bN);
            b2 = *(const float2*)(gb + 16 * bN);
            b3 = *(const float2*)(gb + 17 * bN);
        }
        mma_stage<STG>(aBase, bBase, acc);
        if (ck + 2 < NCH32) {
            cvt_store<0>(sAfill, sBfill, aa, ab, b0, b1, b2, b3);
        }
        __syncthreads();
    }

    // ---------------- epilogue ----------------
    const int mrow = mBlock + warpM * 32 + g;
    const int ncol = nBlock + warpN * 32 + t * 2;

    #pragma unroll
    for (int mf = 0; mf < 2; mf++) {
        const int m = mrow + mf * 16;
        #pragma unroll
        for (int nf = 0; nf < 4; nf++) {
            const int n = ncol + nf * 8;
            float* c = acc[mf][nf];
            if (MODE == 0) {
                *(float2*)(Cout + (size_t)m * N + n)       = make_float2(c[0], c[1]);
                *(float2*)(Cout + (size_t)(m + 8) * N + n) = make_float2(c[2], c[3]);
            } else {
                const int sec = n >> 10;            // 0=q 1=k 2=v
                const int c0i = n & (CH - 1);
                const int h   = c0i >> 6;
                const int d   = c0i & 63;           // even
                const int bIdx = m >> 11;
                const int s    = m & (SEQ - 1);
                const size_t bh = (size_t)(bIdx * HEADS + h);
                if (sec == 2) {
                    const float v0 = vb[c0i], v1 = vb[c0i + 1];
                    float* dst = g_V + (bh * SEQ + (size_t)s) * HDIM + d;
                    *(float2*)dst = make_float2(c[0] + v0, c[1] + v1);
                    *(float2*)(dst + 8 * HDIM) = make_float2(c[2] + v0, c[3] + v1);
                } else {
                    float v0 = c[0], v1 = c[1], v2 = c[2], v3 = c[3];
                    if (sec == 0) {
                        const float q0 = qb[c0i], q1 = qb[c0i + 1];
                        v0 += q0; v1 += q1; v2 += q0; v3 += q1;
                    }
                    const int p = d >> 1;
                    const float sn0 = g_sin[s * HALF + p],       cs0 = g_cos[s * HALF + p];
                    const float sn8 = g_sin[(s + 8) * HALF + p], cs8 = g_cos[(s + 8) * HALF + p];
                    float o0 = v0 * cs0 - v1 * sn0;
                    float o1 = v1 * cs0 + v0 * sn0;
                    float o2 = v2 * cs8 - v3 * sn8;
                    float o3 = v3 * cs8 + v2 * sn8;
                    if (sec == 0) { o0 *= 0.125f; o1 *= 0.125f; o2 *= 0.125f; o3 *= 0.125f; }
                    uint32_t hi0, lo0, hi1, lo1;
                    cvt_pair(o0, o1, hi0, lo0);      // row s
                    cvt_pair(o2, o3, hi1, lo1);      // row s+8
                    const int d2 = d >> 1;
                    if (sec == 0) {
                        uint2* qp = g_Qe + ((bh * SEQ + (size_t)s) * 32 + d2);
                        *qp            = make_uint2(hi0, lo0);
                        *(qp + 8 * 32) = make_uint2(hi1, lo1);
                    } else {
                        uint2* kp = g_Ke + ((bh * 32 + (size_t)d2) * SEQ + s);
                        *kp       = make_uint2(hi0, lo0);
                        *(kp + 8) = make_uint2(hi1, lo1);
                    }
                }
            }
        }
    }
}

// ---------------------------------------------------------------------------
// MMA flash attention: fp16 split-2 3-term, 64x64 tiles, causal.
// 128 threads / 4 warps; warp owns 16 rows x 64 cols (softmax stays in-warp).
// Q frags resident in regs; P repacked C->A layout in regs (no smem trip).
// FIX (round 14 NaN): Q and K smem fills copy 8 x uint4 = 128B per thread
// slice (round 14 copied only 4 -> half of smem uninitialized).
// ---------------------------------------------------------------------------
#define FAR 288                       // Q smem row: 32 entries*8B + 32 pad
#define FBR 544                       // K/V smem row: 64 entries*8B + 32 pad
#define FSMV (32*FBR)                 // V region offset (17408)
#define FSMT (64*FBR)                 // total 34816 (Q tile 64*288=18432 fits)

__global__ __launch_bounds__(128)
void flash_mma_kernel()
{
    __shared__ __align__(16) char sm[FSMT];
    const uint32_t smb = smem_to_u32(sm);
    const int tid = threadIdx.x;
    const int lane = tid & 31;
    const int wm = tid >> 5;          // warp id 0..3
    const int g = lane >> 2;
    const int t = lane & 3;
    const int bh = blockIdx.y;
    const int qt = (gridDim.x - 1) - blockIdx.x;   // largest tiles first
    const int q0 = qt * 64;

    // ---- load Q tile (A layout): 128B per thread slice = 8 x uint4 ----
    {
        const int row = tid >> 1;
        const int half = tid & 1;
        const uint4* src = (const uint4*)(g_Qe
            + ((size_t)(bh * SEQ + q0 + row) * 32 + half * 16));
        const uint32_t dst = smb + (uint32_t)(row * FAR + half * 128);
        #pragma unroll
        for (int i = 0; i < 8; i++) {
            uint4 v = src[i];
            sts128(dst + i * 16, v.x, v.y, v.z, v.w);
        }
    }
    __syncthreads();

    // resident Q fragments
    uint2 aq[4][4];
    {
        const uint32_t abase = smb + (uint32_t)((wm * 16 + g) * FAR + t * 8);
        #pragma unroll
        for (int ks = 0; ks < 4; ks++) {
            aq[ks][0] = lds64(abase + ks * 64);
            aq[ks][1] = lds64(abase + ks * 64 + 8 * FAR);
            aq[ks][2] = lds64(abase + ks * 64 + 32);
            aq[ks][3] = lds64(abase + ks * 64 + 8 * FAR + 32);
        }
    }

    float oacc[8][4];
    #pragma unroll
    for (int nf = 0; nf < 8; nf++)
        #pragma unroll
        for (int j = 0; j < 4; j++) oacc[nf][j] = 0.0f;
    float m0 = -1e30f, m1 = -1e30f, lsum0 = 0.0f, lsum1 = 0.0f;

    for (int kt = 0; kt <= qt; kt++) {
        const int k0 = kt * 64;
        __syncthreads();   // prev tile reads done (also guards Q region reuse)

        // K fill (straight copy of MMA-ready entries): 8 x uint4 per thread
        {
            const int d2 = tid >> 2, seg = tid & 3;
            const uint4* src = (const uint4*)(g_Ke
                + ((size_t)(bh * 32 + d2) * SEQ + k0 + seg * 16));
            const uint32_t dst = smb + (uint32_t)(d2 * FBR + seg * 128);
            #pragma unroll
            for (int i = 0; i < 8; i++) {
                uint4 v = src[i];
                sts128(dst + i * 16, v.x, v.y, v.z, v.w);
            }
        }
        // V fill (convert f32 -> split entries pairing adjacent keys)
        {
            const int s2 = tid >> 2, seg = tid & 3;
            const float* ra = g_V + ((size_t)bh * SEQ + k0 + 2 * s2) * HDIM + seg * 16;
            const float* rb = ra + HDIM;
            const uint32_t dst = smb + FSMV + (uint32_t)(s2 * FBR + seg * 128);
            #pragma unroll
            for (int i = 0; i < 4; i++) {
                float4 va = *(const float4*)(ra + 4 * i);
                float4 vb = *(const float4*)(rb + 4 * i);
                uint32_t h0, l0, h1, l1;
                cvt_pair(va.x, vb.x, h0, l0); cvt_pair(va.y, vb.y, h1, l1);
                sts128(dst + i * 32, h0, l0, h1, l1);
                cvt_pair(va.z, vb.z, h0, l0); cvt_pair(va.w, vb.w, h1, l1);
                sts128(dst + i * 32 + 16, h0, l0, h1, l1);
            }
        }
        __syncthreads();

        // ---- S = Q K^T (3-term) ----
        float sacc[8][4];
        #pragma unroll
        for (int nf = 0; nf < 8; nf++)
            #pragma unroll
            for (int j = 0; j < 4; j++) sacc[nf][j] = 0.0f;

        const uint32_t kb = smb + (uint32_t)(t * FBR + g * 8);
        #pragma unroll
        for (int nf = 0; nf < 8; nf++) {
            #pragma unroll
            for (int ks = 0; ks < 4; ks++) {
                uint2 b0 = lds64(kb + ks * 8 * FBR + nf * 64);
                uint2 b1 = lds64(kb + ks * 8 * FBR + 4 * FBR + nf * 64);
                MMA_F16(sacc[nf], aq[ks][0].x, aq[ks][1].x, aq[ks][2].x, aq[ks][3].x, b0.x, b1.x);
                MMA_F16(sacc[nf], aq[ks][0].x, aq[ks][1].x, aq[ks][2].x, aq[ks][3].x, b0.y, b1.y);
                MMA_F16(sacc[nf], aq[ks][0].y, aq[ks][1].y, aq[ks][2].y, aq[ks][3].y, b0.x, b1.x);
            }
        }

        // causal mask on diagonal tile
        if (kt == qt) {
            const int r0 = wm * 16 + g;
            const int r1 = r0 + 8;
            #pragma unroll
            for (int nf = 0; nf < 8; nf++) {
                const int c = nf * 8 + 2 * t;
                if (c > r0)     sacc[nf][0] = -1e30f;
                if (c + 1 > r0) sacc[nf][1] = -1e30f;
                if (c > r1)     sacc[nf][2] = -1e30f;
                if (c + 1 > r1) sacc[nf][3] = -1e30f;
            }
        }

        // ---- online softmax (rows g, g+8 of this warp) ----
        float mx0 = -1e30f, mx1 = -1e30f;
        #pragma unroll
        for (int nf = 0; nf < 8; nf++) {
            mx0 = fmaxf(mx0, fmaxf(sacc[nf][0], sacc[nf][1]));
            mx1 = fmaxf(mx1, fmaxf(sacc[nf][2], sacc[nf][3]));
        }
        #pragma unroll
        for (int ofs = 1; ofs < 4; ofs <<= 1) {
            mx0 = fmaxf(mx0, __shfl_xor_sync(0xffffffffu, mx0, ofs));
            mx1 = fmaxf(mx1, __shfl_xor_sync(0xffffffffu, mx1, ofs));
        }
        const float mn0 = fmaxf(m0, mx0);
        const float mn1 = fmaxf(m1, mx1);
        const float al0 = __expf(m0 - mn0);
        const float al1 = __expf(m1 - mn1);
        float sum0 = 0.0f, sum1 = 0.0f;
        #pragma unroll
        for (int nf = 0; nf < 8; nf++) {
            sacc[nf][0] = __expf(sacc[nf][0] - mn0);
            sacc[nf][1] = __expf(sacc[nf][1] - mn0);
            sacc[nf][2] = __expf(sacc[nf][2] - mn1);
            sacc[nf][3] = __expf(sacc[nf][3] - mn1);
            sum0 += sacc[nf][0] + sacc[nf][1];
            sum1 += sacc[nf][2] + sacc[nf][3];
        }
        #pragma unroll
        for (int ofs = 1; ofs < 4; ofs <<= 1) {
            sum0 += __shfl_xor_sync(0xffffffffu, sum0, ofs);
            sum1 += __shfl_xor_sync(0xffffffffu, sum1, ofs);
        }
        lsum0 = lsum0 * al0 + sum0;
        lsum1 = lsum1 * al1 + sum1;
        m0 = mn0;
        m1 = mn1;
        #pragma unroll
        for (int nf = 0; nf < 8; nf++) {
            oacc[nf][0] *= al0; oacc[nf][1] *= al0;
            oacc[nf][2] *= al1; oacc[nf][3] *= al1;
        }

        // ---- P: C-layout -> A-frags in regs (hi,lo) ----
        uint2 pa[4][4];
        #pragma unroll
        for (int ks = 0; ks < 4; ks++) {
            cvt_pair(sacc[2*ks][0],   sacc[2*ks][1],   pa[ks][0].x, pa[ks][0].y);
            cvt_pair(sacc[2*ks][2],   sacc[2*ks][3],   pa[ks][1].x, pa[ks][1].y);
            cvt_pair(sacc[2*ks+1][0], sacc[2*ks+1][1], pa[ks][2].x, pa[ks][2].y);
            cvt_pair(sacc[2*ks+1][2], sacc[2*ks+1][3], pa[ks][3].x, pa[ks][3].y);
        }

        // ---- O += P V (3-term) ----
        const uint32_t vbp = smb + FSMV + (uint32_t)(t * FBR + g * 8);
        #pragma unroll
        for (int nf = 0; nf < 8; nf++) {
            #pragma unroll
            for (int ks = 0; ks < 4; ks++) {
                uint2 b0 = lds64(vbp + ks * 8 * FBR + nf * 64);
                uint2 b1 = lds64(vbp + ks * 8 * FBR + 4 * FBR + nf * 64);
                MMA_F16(oacc[nf], pa[ks][0].x, pa[ks][1].x, pa[ks][2].x, pa[ks][3].x, b0.x, b1.x);
                MMA_F16(oacc[nf], pa[ks][0].x, pa[ks][1].x, pa[ks][2].x, pa[ks][3].x, b0.y, b1.y);
                MMA_F16(oacc[nf], pa[ks][0].y, pa[ks][1].y, pa[ks][2].y, pa[ks][3].y, b0.x, b1.x);
            }
        }
    }

    // ---- finalize ----
    const float inv0 = 1.0f / lsum0;
    const float inv1 = 1.0f / lsum1;
    const int b = bh >> 4;
    const int h = bh & 15;
    const int row0 = q0 + wm * 16 + g;
    #pragma unroll
    for (int nf = 0; nf < 8; nf++) {
        const int col = h * 64 + nf * 8 + 2 * t;
        *(float2*)&g_AO[(size_t)(b * SEQ + row0) * CH + col] =
            make_float2(oacc[nf][0] * inv0, oacc[nf][1] * inv0);
        *(float2*)&g_AO[(size_t)(b * SEQ + row0 + 8) * CH + col] =
            make_float2(oacc[nf][2] * inv1, oacc[nf][3] * inv1);
    }
}

// ---------------------------------------------------------------------------
extern "C" void kernel_launch(void* const* d_in, const int* in_sizes, int n_in,
                              void* d_out, int out_size)
{
    const float* x      = (const float*)d_in[0];
    const float* w_qkv  = (const float*)d_in[1];
    const float* q_bias = (const float*)d_in[2];
    const float* v_bias = (const float*)d_in[3];
    const float* w_out  = (const float*)d_in[4];
    float* out = (float*)d_out;

    cudaFuncSetAttribute(gemm_f16<1>,
                         cudaFuncAttributeMaxDynamicSharedMemorySize, SMEM_TOT);
    cudaFuncSetAttribute(gemm_f16<0>,
                         cudaFuncAttributeMaxDynamicSharedMemorySize, SMEM_TOT);

    rope_table_kernel<<<SEQ * HALF / 256, 256>>>();

    // QKV projection + bias/RoPE/scale -> g_Qe/g_Ke (split-fp16), g_V (f32)
    gemm_f16<1><<<dim3(NQKV / 128, MROWS / 128), NTHREADS, SMEM_TOT>>>(
        x, w_qkv, nullptr, q_bias, v_bias, NQKV);

    // causal MMA flash attention -> g_AO
    flash_mma_kernel<<<dim3(SEQ / 64, BATCH * HEADS), 128>>>();

    // output projection -> d_out
    gemm_f16<0><<<dim3(CH / 128, MROWS / 128), NTHREADS, SMEM_TOT>>>(
        nullptr, w_out, out, nullptr, nullptr, CH);
}

// round 16
// speedup vs baseline: 1.9150x; 1.0527x over previous
#include <cuda_runtime.h>
#include <cuda_fp16.h>
#include <math.h>
#include <stdint.h>

// Problem constants
#define BATCH 2
#define SEQ   2048
#define CH    1024
#define HEADS 16
#define HDIM  64
#define MROWS (BATCH*SEQ)   // 4096
#define NQKV  (3*CH)        // 3072
#define HALF  (HDIM/2)      // 32

// ---------------------------------------------------------------------------
// Device scratch. RULE (round 8): NEVER pass device globals as kernel args
// from host code (host shadow symbol aliases host BSS via ATS on GB300).
// ---------------------------------------------------------------------------
__device__ __align__(16) float g_V[(size_t)BATCH*HEADS*SEQ*HDIM];  // [bh][s][d] f32
__device__ __align__(16) float g_AO[(size_t)MROWS*CH];             // attn out f32
__device__ __align__(16) uint2 g_Qe[(size_t)BATCH*HEADS*SEQ*32];   // [bh][s][d2] split-fp16
__device__ __align__(16) uint2 g_Ke[(size_t)BATCH*HEADS*32*SEQ];   // [bh][d2][s] split-fp16
__device__ __align__(16) float g_sin[SEQ*HALF];
__device__ __align__(16) float g_cos[SEQ*HALF];

// ---------------------------------------------------------------------------
// Helpers
// ---------------------------------------------------------------------------
__device__ __forceinline__ uint32_t smem_to_u32(const void* p) {
    uint32_t a;
    asm("{ .reg .u64 t; cvta.to.shared.u64 t, %1; cvt.u32.u64 %0, t; }"
        : "=r"(a) : "l"(p));
    return a;
}
__device__ __forceinline__ uint2 lds64(uint32_t a) {
    uint2 v;
    asm volatile("ld.shared.v2.b32 {%0,%1}, [%2];" : "=r"(v.x), "=r"(v.y) : "r"(a));
    return v;
}
__device__ __forceinline__ void sts128(uint32_t a, uint32_t x, uint32_t y,
                                       uint32_t z, uint32_t w) {
    asm volatile("st.shared.v4.b32 [%0], {%1,%2,%3,%4};"
                 :: "r"(a), "r"(x), "r"(y), "r"(z), "r"(w));
}
// split two floats into packed fp16 (hi-pair, lo-pair)
__device__ __forceinline__ void cvt_pair(float x, float y,
                                         uint32_t& hi, uint32_t& lo) {
    __half hx = __float2half_rn(x), hy = __float2half_rn(y);
    float rx = x - __half2float(hx), ry = y - __half2float(hy);
    __half lx = __float2half_rn(rx), ly = __float2half_rn(ry);
    hi = (uint32_t)__half_as_ushort(hx) | ((uint32_t)__half_as_ushort(hy) << 16);
    lo = (uint32_t)__half_as_ushort(lx) | ((uint32_t)__half_as_ushort(ly) << 16);
}
#define MMA_F16(c,a0,a1,a2,a3,b0,b1) \
    asm volatile("mma.sync.aligned.m16n8k16.row.col.f32.f16.f16.f32 " \
        "{%0,%1,%2,%3}, {%4,%5,%6,%7}, {%8,%9}, {%0,%1,%2,%3};" \
        : "+f"((c)[0]),"+f"((c)[1]),"+f"((c)[2]),"+f"((c)[3]) \
        : "r"(a0),"r"(a1),"r"(a2),"r"(a3), "r"(b0),"r"(b1))

// ---------------------------------------------------------------------------
// RoPE table
// ---------------------------------------------------------------------------
__global__ void rope_table_kernel() {
    int idx = blockIdx.x * blockDim.x + threadIdx.x;
    if (idx < SEQ * HALF) {
        int s = idx >> 5;
        int p = idx & 31;
        float dim_t = powf(10000.0f, (float)p / (float)HALF);
        float ang = (float)s / dim_t;
        g_sin[idx] = sinf(ang);
        g_cos[idx] = cosf(ang);
    }
}

// ---------------------------------------------------------------------------
// FP16 split-2 3-term MMA GEMM (round-13 verified core): C = A.B, fp32 IO.
// MODE 0: A = g_AO (device symbol), plain store.
// MODE 1: QKV epilogue -> g_Qe/g_Ke (split-fp16 MMA-ready), g_V (f32).
// ---------------------------------------------------------------------------
#define AR2 160
#define BR2 1056
#define AT2 (128*AR2)
#define BT2 (16*BR2)
#define STG (AT2+BT2)
#define SMEM_TOT (2*STG)
#define NCH32 (CH/32)
#define NTHREADS 512

template <int SOFF>
__device__ __forceinline__ void mma_stage(uint32_t aBase, uint32_t bBase,
                                          float (&acc)[2][4][4])
{
    #pragma unroll
    for (int ks = 0; ks < 2; ks++) {
        uint2 b0[4], b1[4];
        #pragma unroll
        for (int nf = 0; nf < 4; nf++) {
            b0[nf] = lds64(bBase + SOFF + ks * 8 * BR2 + nf * 64);
            b1[nf] = lds64(bBase + SOFF + ks * 8 * BR2 + 4 * BR2 + nf * 64);
        }
        #pragma unroll
        for (int mf = 0; mf < 2; mf++) {
            const uint32_t ab = aBase + SOFF + mf * 16 * AR2 + ks * 64;
            uint2 a0 = lds64(ab);
            uint2 a1 = lds64(ab + 8 * AR2);
            uint2 a2 = lds64(ab + 32);
            uint2 a3 = lds64(ab + 8 * AR2 + 32);
            #pragma unroll
            for (int nf = 0; nf < 4; nf++) {
                MMA_F16(acc[mf][nf], a0.x, a1.x, a2.x, a3.x, b0[nf].x, b1[nf].x);
                MMA_F16(acc[mf][nf], a0.x, a1.x, a2.x, a3.x, b0[nf].y, b1[nf].y);
                MMA_F16(acc[mf][nf], a0.y, a1.y, a2.y, a3.y, b0[nf].x, b1[nf].x);
            }
        }
    }
}

template <int SOFF>
__device__ __forceinline__ void cvt_store(uint32_t sAfill, uint32_t sBfill,
                                          float4 aa, float4 ab,
                                          float2 b0, float2 b1,
                                          float2 b2, float2 b3)
{
    uint32_t h0, l0, h1, l1;
    cvt_pair(aa.x, aa.y, h0, l0); cvt_pair(aa.z, aa.w, h1, l1);
    sts128(sAfill + SOFF, h0, l0, h1, l1);
    cvt_pair(ab.x, ab.y, h0, l0); cvt_pair(ab.z, ab.w, h1, l1);
    sts128(sAfill + SOFF + 64, h0, l0, h1, l1);
    cvt_pair(b0.x, b1.x, h0, l0); cvt_pair(b0.y, b1.y, h1, l1);
    sts128(sBfill + SOFF, h0, l0, h1, l1);
    cvt_pair(b2.x, b3.x, h0, l0); cvt_pair(b2.y, b3.y, h1, l1);
    sts128(sBfill + SOFF + 8 * BR2, h0, l0, h1, l1);
}

template <int MODE>
__global__ __launch_bounds__(NTHREADS, 1)
void gemm_f16(const float* __restrict__ A, const float* __restrict__ Bm,
              float* __restrict__ Cout,
              const float* __restrict__ qb, const float* __restrict__ vb,
              int N)
{
    extern __shared__ __align__(16) char sm[];
    const uint32_t smb = smem_to_u32(sm);

    const int tid  = threadIdx.x;
    const int lane = tid & 31;
    const int wid  = tid >> 5;
    const int warpM = wid & 3;
    const int warpN = wid >> 2;
    const int mBlock = blockIdx.y * 128;
    const int nBlock = blockIdx.x * 128;
    const int g = lane >> 2;
    const int t = lane & 3;

    const float* Abase = (MODE == 0) ? (const float*)g_AO : A;

    const int arow = tid >> 2;
    const int aq   = tid & 3;
    const float* gA = Abase + (size_t)(mBlock + arow) * CH + aq * 4;
    const uint32_t sAfill = smb + (uint32_t)(arow * AR2 + aq * 16);

    const int kk = tid >> 6;
    const int n2 = tid & 63;
    const float* gB = Bm + (size_t)(2 * kk) * N + nBlock + 2 * n2;
    const uint32_t sBfill = smb + AT2 + (uint32_t)(kk * BR2 + n2 * 16);

    const uint32_t aBase = smb + (uint32_t)((warpM * 32 + g) * AR2 + t * 8);
    const uint32_t bBase = smb + AT2 + (uint32_t)(t * BR2 + (warpN * 32 + g) * 8);

    float acc[2][4][4];
    #pragma unroll
    for (int i = 0; i < 2; i++)
        #pragma unroll
        for (int j = 0; j < 4; j++)
            #pragma unroll
            for (int k = 0; k < 4; k++) acc[i][j][k] = 0.0f;

    const size_t bN = (size_t)N;

    float4 aa = *(const float4*)(gA);
    float4 ab = *(const float4*)(gA + 16);
    float2 b0 = *(const float2*)(gB);
    float2 b1 = *(const float2*)(gB + bN);
    float2 b2 = *(const float2*)(gB + 16 * bN);
    float2 b3 = *(const float2*)(gB + 17 * bN);
    cvt_store<0>(sAfill, sBfill, aa, ab, b0, b1, b2, b3);
    __syncthreads();

    #pragma unroll 1
    for (int ck = 0; ck < NCH32; ck += 2) {
        {
            const int ko = (ck + 1) * 32;
            aa = *(const float4*)(gA + ko);
            ab = *(const float4*)(gA + ko + 16);
            const float* gb = gB + (size_t)ko * bN;
            b0 = *(const float2*)(gb);
            b1 = *(const float2*)(gb + bN);
            b2 = *(const float2*)(gb + 16 * bN);
            b3 = *(const float2*)(gb + 17 * bN);
        }
        mma_stage<0>(aBase, bBase, acc);
        cvt_store<STG>(sAfill, sBfill, aa, ab, b0, b1, b2, b3);
        __syncthreads();

        if (ck + 2 < NCH32) {
            const int ko = (ck + 2) * 32;
            aa = *(const float4*)(gA + ko);
            ab = *(const float4*)(gA + ko + 16);
            const float* gb = gB + (size_t)ko * bN;
            b0 = *(const float2*)(gb);
            b1 = *(const float2*)(gb + bN);
            b2 = *(const float2*)(gb + 16 * bN);
            b3 = *(const float2*)(gb + 17 * bN);
        }
        mma_stage<STG>(aBase, bBase, acc);
        if (ck + 2 < NCH32) {
            cvt_store<0>(sAfill, sBfill, aa, ab, b0, b1, b2, b3);
        }
        __syncthreads();
    }

    // ---------------- epilogue ----------------
    const int mrow = mBlock + warpM * 32 + g;
    const int ncol = nBlock + warpN * 32 + t * 2;

    #pragma unroll
    for (int mf = 0; mf < 2; mf++) {
        const int m = mrow + mf * 16;
        #pragma unroll
        for (int nf = 0; nf < 4; nf++) {
            const int n = ncol + nf * 8;
            float* c = acc[mf][nf];
            if (MODE == 0) {
                *(float2*)(Cout + (size_t)m * N + n)       = make_float2(c[0], c[1]);
                *(float2*)(Cout + (size_t)(m + 8) * N + n) = make_float2(c[2], c[3]);
            } else {
                const int sec = n >> 10;            // 0=q 1=k 2=v
                const int c0i = n & (CH - 1);
                const int h   = c0i >> 6;
                const int d   = c0i & 63;           // even
                const int bIdx = m >> 11;
                const int s    = m & (SEQ - 1);
                const size_t bh = (size_t)(bIdx * HEADS + h);
                if (sec == 2) {
                    const float v0 = vb[c0i], v1 = vb[c0i + 1];
                    float* dst = g_V + (bh * SEQ + (size_t)s) * HDIM + d;
                    *(float2*)dst = make_float2(c[0] + v0, c[1] + v1);
                    *(float2*)(dst + 8 * HDIM) = make_float2(c[2] + v0, c[3] + v1);
                } else {
                    float v0 = c[0], v1 = c[1], v2 = c[2], v3 = c[3];
                    if (sec == 0) {
                        const float q0 = qb[c0i], q1 = qb[c0i + 1];
                        v0 += q0; v1 += q1; v2 += q0; v3 += q1;
                    }
                    const int p = d >> 1;
                    const float sn0 = g_sin[s * HALF + p],       cs0 = g_cos[s * HALF + p];
                    const float sn8 = g_sin[(s + 8) * HALF + p], cs8 = g_cos[(s + 8) * HALF + p];
                    float o0 = v0 * cs0 - v1 * sn0;
                    float o1 = v1 * cs0 + v0 * sn0;
                    float o2 = v2 * cs8 - v3 * sn8;
                    float o3 = v3 * cs8 + v2 * sn8;
                    if (sec == 0) { o0 *= 0.125f; o1 *= 0.125f; o2 *= 0.125f; o3 *= 0.125f; }
                    uint32_t hi0, lo0, hi1, lo1;
                    cvt_pair(o0, o1, hi0, lo0);      // row s
                    cvt_pair(o2, o3, hi1, lo1);      // row s+8
                    const int d2 = d >> 1;
                    if (sec == 0) {
                        uint2* qp = g_Qe + ((bh * SEQ + (size_t)s) * 32 + d2);
                        *qp            = make_uint2(hi0, lo0);
                        *(qp + 8 * 32) = make_uint2(hi1, lo1);
                    } else {
                        uint2* kp = g_Ke + ((bh * 32 + (size_t)d2) * SEQ + s);
                        *kp       = make_uint2(hi0, lo0);
                        *(kp + 8) = make_uint2(hi1, lo1);
                    }
                }
            }
        }
    }
}

// ---------------------------------------------------------------------------
// MMA flash attention v2: fp16 split-2 3-term, 128x64 tiles, causal.
// 256 threads / 8 warps; warp owns 16 q-rows x 64 k-cols. K/V fill + syncs
// amortized over 2x rows vs v1. Q smem (36864B) overlays K/V (34816B): Q is
// register-resident after the prologue. Final diagonal k-tile skipped by the
// lower 4 warps (fully masked rows), warp-uniform branch, syncs unconditional.
// ---------------------------------------------------------------------------
#define FAR 288                       // Q smem row: 32 entries*8B + 32 pad
#define FBR 544                       // K/V smem row: 64 entries*8B + 32 pad
#define FSMV (32*FBR)                 // V region offset (17408)
#define FSMT (128*FAR)                // 36864 total (>= K+V 34816)

__global__ __launch_bounds__(256)
void flash_mma_kernel()
{
    __shared__ __align__(16) char sm[FSMT];
    const uint32_t smb = smem_to_u32(sm);
    const int tid = threadIdx.x;
    const int lane = tid & 31;
    const int wm = tid >> 5;          // warp id 0..7 (rows wm*16..wm*16+15)
    const int g = lane >> 2;
    const int t = lane & 3;
    const int bh = blockIdx.y;
    const int qt = (gridDim.x - 1) - blockIdx.x;   // largest tiles first
    const int q0 = qt * 128;
    const int ktmax = 2 * qt + 1;

    // ---- load Q tile (A layout): 128 rows, 128B per thread slice ----
    {
        const int row = tid >> 1;
        const int half = tid & 1;
        const uint4* src = (const uint4*)(g_Qe
            + ((size_t)(bh * SEQ + q0 + row) * 32 + half * 16));
        const uint32_t dst = smb + (uint32_t)(row * FAR + half * 128);
        #pragma unroll
        for (int i = 0; i < 8; i++) {
            uint4 v = src[i];
            sts128(dst + i * 16, v.x, v.y, v.z, v.w);
        }
    }
    __syncthreads();

    // resident Q fragments
    uint2 aq[4][4];
    {
        const uint32_t abase = smb + (uint32_t)((wm * 16 + g) * FAR + t * 8);
        #pragma unroll
        for (int ks = 0; ks < 4; ks++) {
            aq[ks][0] = lds64(abase + ks * 64);
            aq[ks][1] = lds64(abase + ks * 64 + 8 * FAR);
            aq[ks][2] = lds64(abase + ks * 64 + 32);
            aq[ks][3] = lds64(abase + ks * 64 + 8 * FAR + 32);
        }
    }

    float oacc[8][4];
    #pragma unroll
    for (int nf = 0; nf < 8; nf++)
        #pragma unroll
        for (int j = 0; j < 4; j++) oacc[nf][j] = 0.0f;
    float m0 = -1e30f, m1 = -1e30f, lsum0 = 0.0f, lsum1 = 0.0f;

    for (int kt = 0; kt <= ktmax; kt++) {
        const int k0 = kt * 64;
        __syncthreads();   // prev tile reads done (also guards Q region reuse)

        // K fill: 32 d2-rows x 512B; 8 threads/row x 64B (4 x uint4)
        {
            const int d2 = tid >> 3, seg = tid & 7;
            const uint4* src = (const uint4*)(g_Ke
                + ((size_t)(bh * 32 + d2) * SEQ + k0 + seg * 8));
            const uint32_t dst = smb + (uint32_t)(d2 * FBR + seg * 64);
            #pragma unroll
            for (int i = 0; i < 4; i++) {
                uint4 v = src[i];
                sts128(dst + i * 16, v.x, v.y, v.z, v.w);
            }
        }
        // V fill: 32 s2-rows; 8 threads/row, each converts 8 d-values x 2 keys
        {
            const int s2 = tid >> 3, seg = tid & 7;
            const float* ra = g_V + ((size_t)bh * SEQ + k0 + 2 * s2) * HDIM + seg * 8;
            const float* rb = ra + HDIM;
            const uint32_t dst = smb + FSMV + (uint32_t)(s2 * FBR + seg * 64);
            #pragma unroll
            for (int i = 0; i < 2; i++) {
                float4 va = *(const float4*)(ra + 4 * i);
                float4 vb = *(const float4*)(rb + 4 * i);
                uint32_t h0, l0, h1, l1;
                cvt_pair(va.x, vb.x, h0, l0); cvt_pair(va.y, vb.y, h1, l1);
                sts128(dst + i * 32, h0, l0, h1, l1);
                cvt_pair(va.z, vb.z, h0, l0); cvt_pair(va.w, vb.w, h1, l1);
                sts128(dst + i * 32 + 16, h0, l0, h1, l1);
            }
        }
        __syncthreads();

        // lower 4 warps (rows 0..63) fully masked on the last diagonal tile
        if (kt == ktmax && wm < 4) continue;

        // ---- S = Q K^T (3-term) ----
        float sacc[8][4];
        #pragma unroll
        for (int nf = 0; nf < 8; nf++)
            #pragma unroll
            for (int j = 0; j < 4; j++) sacc[nf][j] = 0.0f;

        const uint32_t kb = smb + (uint32_t)(t * FBR + g * 8);
        #pragma unroll
        for (int nf = 0; nf < 8; nf++) {
            #pragma unroll
            for (int ks = 0; ks < 4; ks++) {
                uint2 b0 = lds64(kb + ks * 8 * FBR + nf * 64);
                uint2 b1 = lds64(kb + ks * 8 * FBR + 4 * FBR + nf * 64);
                MMA_F16(sacc[nf], aq[ks][0].x, aq[ks][1].x, aq[ks][2].x, aq[ks][3].x, b0.x, b1.x);
                MMA_F16(sacc[nf], aq[ks][0].x, aq[ks][1].x, aq[ks][2].x, aq[ks][3].x, b0.y, b1.y);
                MMA_F16(sacc[nf], aq[ks][0].y, aq[ks][1].y, aq[ks][2].y, aq[ks][3].y, b0.x, b1.x);
            }
        }

        // causal mask on diagonal-crossing tiles (koff = 0 or 64)
        if (kt >= ktmax - 1) {
            const int koff = k0 - q0;               // tile-relative col offset
            const int r0 = wm * 16 + g - koff;
            const int r1 = r0 + 8;
            #pragma unroll
            for (int nf = 0; nf < 8; nf++) {
                const int c = nf * 8 + 2 * t;
                if (c > r0)     sacc[nf][0] = -1e30f;
                if (c + 1 > r0) sacc[nf][1] = -1e30f;
                if (c > r1)     sacc[nf][2] = -1e30f;
                if (c + 1 > r1) sacc[nf][3] = -1e30f;
            }
        }

        // ---- online softmax (rows g, g+8 of this warp) ----
        float mx0 = -1e30f, mx1 = -1e30f;
        #pragma unroll
        for (int nf = 0; nf < 8; nf++) {
            mx0 = fmaxf(mx0, fmaxf(sacc[nf][0], sacc[nf][1]));
            mx1 = fmaxf(mx1, fmaxf(sacc[nf][2], sacc[nf][3]));
        }
        #pragma unroll
        for (int ofs = 1; ofs < 4; ofs <<= 1) {
            mx0 = fmaxf(mx0, __shfl_xor_sync(0xffffffffu, mx0, ofs));
            mx1 = fmaxf(mx1, __shfl_xor_sync(0xffffffffu, mx1, ofs));
        }
        const float mn0 = fmaxf(m0, mx0);
        const float mn1 = fmaxf(m1, mx1);
        const float al0 = __expf(m0 - mn0);
        const float al1 = __expf(m1 - mn1);
        float sum0 = 0.0f, sum1 = 0.0f;
        #pragma unroll
        for (int nf = 0; nf < 8; nf++) {
            sacc[nf][0] = __expf(sacc[nf][0] - mn0);
            sacc[nf][1] = __expf(sacc[nf][1] - mn0);
            sacc[nf][2] = __expf(sacc[nf][2] - mn1);
            sacc[nf][3] = __expf(sacc[nf][3] - mn1);
            sum0 += sacc[nf][0] + sacc[nf][1];
            sum1 += sacc[nf][2] + sacc[nf][3];
        }
        #pragma unroll
        for (int ofs = 1; ofs < 4; ofs <<= 1) {
            sum0 += __shfl_xor_sync(0xffffffffu, sum0, ofs);
            sum1 += __shfl_xor_sync(0xffffffffu, sum1, ofs);
        }
        lsum0 = lsum0 * al0 + sum0;
        lsum1 = lsum1 * al1 + sum1;
        m0 = mn0;
        m1 = mn1;
        #pragma unroll
        for (int nf = 0; nf < 8; nf++) {
            oacc[nf][0] *= al0; oacc[nf][1] *= al0;
            oacc[nf][2] *= al1; oacc[nf][3] *= al1;
        }

        // ---- P: C-layout -> A-frags in regs (hi,lo) ----
        uint2 pa[4][4];
        #pragma unroll
        for (int ks = 0; ks < 4; ks++) {
            cvt_pair(sacc[2*ks][0],   sacc[2*ks][1],   pa[ks][0].x, pa[ks][0].y);
            cvt_pair(sacc[2*ks][2],   sacc[2*ks][3],   pa[ks][1].x, pa[ks][1].y);
            cvt_pair(sacc[2*ks+1][0], sacc[2*ks+1][1], pa[ks][2].x, pa[ks][2].y);
            cvt_pair(sacc[2*ks+1][2], sacc[2*ks+1][3], pa[ks][3].x, pa[ks][3].y);
        }

        // ---- O += P V (3-term) ----
        const uint32_t vbp = smb + FSMV + (uint32_t)(t * FBR + g * 8);
        #pragma unroll
        for (int nf = 0; nf < 8; nf++) {
            #pragma unroll
            for (int ks = 0; ks < 4; ks++) {
                uint2 b0 = lds64(vbp + ks * 8 * FBR + nf * 64);
                uint2 b1 = lds64(vbp + ks * 8 * FBR + 4 * FBR + nf * 64);
                MMA_F16(oacc[nf], pa[ks][0].x, pa[ks][1].x, pa[ks][2].x, pa[ks][3].x, b0.x, b1.x);
                MMA_F16(oacc[nf], pa[ks][0].x, pa[ks][1].x, pa[ks][2].x, pa[ks][3].x, b0.y, b1.y);
                MMA_F16(oacc[nf], pa[ks][0].y, pa[ks][1].y, pa[ks][2].y, pa[ks][3].y, b0.x, b1.x);
            }
        }
    }

    // ---- finalize ----
    const float inv0 = 1.0f / lsum0;
    const float inv1 = 1.0f / lsum1;
    const int b = bh >> 4;
    const int h = bh & 15;
    const int row0 = q0 + wm * 16 + g;
    #pragma unroll
    for (int nf = 0; nf < 8; nf++) {
        const int col = h * 64 + nf * 8 + 2 * t;
        *(float2*)&g_AO[(size_t)(b * SEQ + row0) * CH + col] =
            make_float2(oacc[nf][0] * inv0, oacc[nf][1] * inv0);
        *(float2*)&g_AO[(size_t)(b * SEQ + row0 + 8) * CH + col] =
            make_float2(oacc[nf][2] * inv1, oacc[nf][3] * inv1);
    }
}

// ---------------------------------------------------------------------------
extern "C" void kernel_launch(void* const* d_in, const int* in_sizes, int n_in,
                              void* d_out, int out_size)
{
    const float* x      = (const float*)d_in[0];
    const float* w_qkv  = (const float*)d_in[1];
    const float* q_bias = (const float*)d_in[2];
    const float* v_bias = (const float*)d_in[3];
    const float* w_out  = (const float*)d_in[4];
    float* out = (float*)d_out;

    cudaFuncSetAttribute(gemm_f16<1>,
                         cudaFuncAttributeMaxDynamicSharedMemorySize, SMEM_TOT);
    cudaFuncSetAttribute(gemm_f16<0>,
                         cudaFuncAttributeMaxDynamicSharedMemorySize, SMEM_TOT);

    rope_table_kernel<<<SEQ * HALF / 256, 256>>>();

    // QKV projection + bias/RoPE/scale -> g_Qe/g_Ke (split-fp16), g_V (f32)
    gemm_f16<1><<<dim3(NQKV / 128, MROWS / 128), NTHREADS, SMEM_TOT>>>(
        x, w_qkv, nullptr, q_bias, v_bias, NQKV);

    // causal MMA flash attention (128-row q-tiles, 8 warps) -> g_AO
    flash_mma_kernel<<<dim3(SEQ / 128, BATCH * HEADS), 256>>>();

    // output projection -> d_out
    gemm_f16<0><<<dim3(CH / 128, MROWS / 128), NTHREADS, SMEM_TOT>>>(
        nullptr, w_out, out, nullptr, nullptr, CH);
}

// round 17
// speedup vs baseline: 2.0596x; 1.0755x over previous
#include <cuda_runtime.h>
#include <cuda_fp16.h>
#include <math.h>
#include <stdint.h>

// Problem constants
#define BATCH 2
#define SEQ   2048
#define CH    1024
#define HEADS 16
#define HDIM  64
#define MROWS (BATCH*SEQ)   // 4096
#define NQKV  (3*CH)        // 3072
#define HALF  (HDIM/2)      // 32
#define K2N   (CH/2)        // 512 k2 entries per row

// ---------------------------------------------------------------------------
// Device scratch. RULE (round 8): NEVER pass device globals as kernel args
// from host code (host shadow symbol aliases host BSS via ATS on GB300).
// Split-fp16 entry = uint2(hi_half2, lo_half2) packing two adjacent values.
// ---------------------------------------------------------------------------
__device__ __align__(16) float g_V[(size_t)BATCH*HEADS*SEQ*HDIM];  // [bh][s][d] f32
__device__ __align__(16) uint2 g_Qe[(size_t)BATCH*HEADS*SEQ*32];   // [bh][s][d2]
__device__ __align__(16) uint2 g_Ke[(size_t)BATCH*HEADS*32*SEQ];   // [bh][d2][s]
__device__ __align__(16) uint2 g_Xe [(size_t)MROWS*K2N];           // x,   A-layout
__device__ __align__(16) uint2 g_AOe[(size_t)MROWS*K2N];           // attn, A-layout
__device__ __align__(16) uint2 g_Wqe[(size_t)K2N*NQKV];            // w_qkv, B-layout [k2][n]
__device__ __align__(16) uint2 g_Woe[(size_t)K2N*CH];              // w_out, B-layout [k2][n]
__device__ __align__(16) float g_sin[SEQ*HALF];
__device__ __align__(16) float g_cos[SEQ*HALF];

// ---------------------------------------------------------------------------
// Helpers
// ---------------------------------------------------------------------------
__device__ __forceinline__ uint32_t smem_to_u32(const void* p) {
    uint32_t a;
    asm("{ .reg .u64 t; cvta.to.shared.u64 t, %1; cvt.u32.u64 %0, t; }"
        : "=r"(a) : "l"(p));
    return a;
}
__device__ __forceinline__ uint2 lds64(uint32_t a) {
    uint2 v;
    asm volatile("ld.shared.v2.b32 {%0,%1}, [%2];" : "=r"(v.x), "=r"(v.y) : "r"(a));
    return v;
}
__device__ __forceinline__ void sts128(uint32_t a, uint32_t x, uint32_t y,
                                       uint32_t z, uint32_t w) {
    asm volatile("st.shared.v4.b32 [%0], {%1,%2,%3,%4};"
                 :: "r"(a), "r"(x), "r"(y), "r"(z), "r"(w));
}
// split two floats into packed fp16 (hi-pair, lo-pair)
__device__ __forceinline__ void cvt_pair(float x, float y,
                                         uint32_t& hi, uint32_t& lo) {
    __half hx = __float2half_rn(x), hy = __float2half_rn(y);
    float rx = x - __half2float(hx), ry = y - __half2float(hy);
    __half lx = __float2half_rn(rx), ly = __float2half_rn(ry);
    hi = (uint32_t)__half_as_ushort(hx) | ((uint32_t)__half_as_ushort(hy) << 16);
    lo = (uint32_t)__half_as_ushort(lx) | ((uint32_t)__half_as_ushort(ly) << 16);
}
#define MMA_F16(c,a0,a1,a2,a3,b0,b1) \
    asm volatile("mma.sync.aligned.m16n8k16.row.col.f32.f16.f16.f32 " \
        "{%0,%1,%2,%3}, {%4,%5,%6,%7}, {%8,%9}, {%0,%1,%2,%3};" \
        : "+f"((c)[0]),"+f"((c)[1]),"+f"((c)[2]),"+f"((c)[3]) \
        : "r"(a0),"r"(a1),"r"(a2),"r"(a3), "r"(b0),"r"(b1))

// ---------------------------------------------------------------------------
// RoPE table
// ---------------------------------------------------------------------------
__global__ void rope_table_kernel() {
    int idx = blockIdx.x * blockDim.x + threadIdx.x;
    if (idx < SEQ * HALF) {
        int s = idx >> 5;
        int p = idx & 31;
        float dim_t = powf(10000.0f, (float)p / (float)HALF);
        float ang = (float)s / dim_t;
        g_sin[idx] = sinf(ang);
        g_cos[idx] = cosf(ang);
    }
}

// ---------------------------------------------------------------------------
// One-time operand converters (f32 -> split-fp16 MMA-ready layouts)
// ---------------------------------------------------------------------------
// x [m][k] -> g_Xe [m][k2]
__global__ void convert_x_kernel(const float* __restrict__ x) {
    int idx = blockIdx.x * blockDim.x + threadIdx.x;   // m*512 + k2
    float2 v = *(const float2*)(x + 2 * (size_t)idx);
    uint32_t hi, lo;
    cvt_pair(v.x, v.y, hi, lo);
    g_Xe[idx] = make_uint2(hi, lo);
}
// w [k][n] -> We [k2][n] (pairs adjacent k rows). WHICH 0 -> g_Wqe, 1 -> g_Woe.
template <int WHICH>
__global__ void convert_w_kernel(const float* __restrict__ w, int N) {
    const int n  = blockIdx.x * blockDim.x + threadIdx.x;
    const int k2 = blockIdx.y;
    float a = w[(size_t)(2 * k2) * N + n];
    float b = w[(size_t)(2 * k2 + 1) * N + n];
    uint32_t hi, lo;
    cvt_pair(a, b, hi, lo);
    uint2* We = (WHICH == 0) ? g_Wqe : g_Woe;
    We[(size_t)k2 * N + n] = make_uint2(hi, lo);
}

// ---------------------------------------------------------------------------
// FP16 split-2 3-term MMA GEMM v6: operands pre-split in gmem; fill = pure
// copy (2x LDG.128 + 2x STS.128 per operand per thread per chunk).
// Verified v5 smem geometry / mma_stage / epilogues unchanged.
// MODE 0: A = g_AOe, B = g_Woe, plain f32 store.
// MODE 1: A = g_Xe,  B = g_Wqe, fused QKV epilogue -> g_Qe/g_Ke/g_V.
// ---------------------------------------------------------------------------
#define AR2 160
#define BR2 1056
#define AT2 (128*AR2)
#define BT2 (16*BR2)
#define STG (AT2+BT2)
#define SMEM_TOT (2*STG)
#define NCH32 (CH/32)                 // 32 chunks (16 k2-rows each)
#define NTHREADS 512

template <int SOFF>
__device__ __forceinline__ void mma_stage(uint32_t aBase, uint32_t bBase,
                                          float (&acc)[2][4][4])
{
    #pragma unroll
    for (int ks = 0; ks < 2; ks++) {
        uint2 b0[4], b1[4];
        #pragma unroll
        for (int nf = 0; nf < 4; nf++) {
            b0[nf] = lds64(bBase + SOFF + ks * 8 * BR2 + nf * 64);
            b1[nf] = lds64(bBase + SOFF + ks * 8 * BR2 + 4 * BR2 + nf * 64);
        }
        #pragma unroll
        for (int mf = 0; mf < 2; mf++) {
            const uint32_t ab = aBase + SOFF + mf * 16 * AR2 + ks * 64;
            uint2 a0 = lds64(ab);
            uint2 a1 = lds64(ab + 8 * AR2);
            uint2 a2 = lds64(ab + 32);
            uint2 a3 = lds64(ab + 8 * AR2 + 32);
            #pragma unroll
            for (int nf = 0; nf < 4; nf++) {
                MMA_F16(acc[mf][nf], a0.x, a1.x, a2.x, a3.x, b0[nf].x, b1[nf].x);
                MMA_F16(acc[mf][nf], a0.x, a1.x, a2.x, a3.x, b0[nf].y, b1[nf].y);
                MMA_F16(acc[mf][nf], a0.y, a1.y, a2.y, a3.y, b0[nf].x, b1[nf].x);
            }
        }
    }
}

template <int MODE>
__global__ __launch_bounds__(NTHREADS, 1)
void gemm_f16(float* __restrict__ Cout,
              const float* __restrict__ qb, const float* __restrict__ vb,
              int N)
{
    extern __shared__ __align__(16) char sm[];
    const uint32_t smb = smem_to_u32(sm);

    const int tid  = threadIdx.x;
    const int lane = tid & 31;
    const int wid  = tid >> 5;
    const int warpM = wid & 3;
    const int warpN = wid >> 2;
    const int mBlock = blockIdx.y * 128;
    const int nBlock = blockIdx.x * 128;
    const int g = lane >> 2;
    const int t = lane & 3;

    // device-side symbol selection (pointer rule)
    const uint2* Ae = (MODE == 0) ? g_AOe : g_Xe;
    const uint2* We = (MODE == 0) ? g_Woe : g_Wqe;

    // A loader: 32B (4 entries) per thread per chunk
    const int arow = tid >> 2;
    const int aq   = tid & 3;
    const uint2* gA = Ae + (size_t)(mBlock + arow) * K2N + aq * 4;
    const uint32_t sAfill = smb + (uint32_t)(arow * AR2 + aq * 32);

    // B loader: 32B (4 n-entries) per thread per chunk, k2-row per 32 threads
    const int k2row = tid >> 5;           // 0..15
    const int nseg  = tid & 31;           // 0..31
    const uint2* gB = We + (size_t)k2row * N + nBlock + nseg * 4;
    const uint32_t sBfill = smb + AT2 + (uint32_t)(k2row * BR2 + nseg * 32);

    const uint32_t aBase = smb + (uint32_t)((warpM * 32 + g) * AR2 + t * 8);
    const uint32_t bBase = smb + AT2 + (uint32_t)(t * BR2 + (warpN * 32 + g) * 8);

    float acc[2][4][4];
    #pragma unroll
    for (int i = 0; i < 2; i++)
        #pragma unroll
        for (int j = 0; j < 4; j++)
            #pragma unroll
            for (int k = 0; k < 4; k++) acc[i][j][k] = 0.0f;

    const size_t bStride = (size_t)16 * N;   // entries per chunk of B

    uint4 a0 = *(const uint4*)(gA);
    uint4 a1 = *(const uint4*)(gA + 2);
    uint4 b0 = *(const uint4*)(gB);
    uint4 b1 = *(const uint4*)(gB + 2);
    sts128(sAfill,      a0.x, a0.y, a0.z, a0.w);
    sts128(sAfill + 16, a1.x, a1.y, a1.z, a1.w);
    sts128(sBfill,      b0.x, b0.y, b0.z, b0.w);
    sts128(sBfill + 16, b1.x, b1.y, b1.z, b1.w);
    __syncthreads();

    #pragma unroll 1
    for (int ck = 0; ck < NCH32; ck += 2) {
        {
            const uint2* ga = gA + (ck + 1) * 16;
            const uint2* gb = gB + (size_t)(ck + 1) * bStride;
            a0 = *(const uint4*)(ga);
            a1 = *(const uint4*)(ga + 2);
            b0 = *(const uint4*)(gb);
            b1 = *(const uint4*)(gb + 2);
        }
        mma_stage<0>(aBase, bBase, acc);
        sts128(sAfill + STG,      a0.x, a0.y, a0.z, a0.w);
        sts128(sAfill + STG + 16, a1.x, a1.y, a1.z, a1.w);
        sts128(sBfill + STG,      b0.x, b0.y, b0.z, b0.w);
        sts128(sBfill + STG + 16, b1.x, b1.y, b1.z, b1.w);
        __syncthreads();

        if (ck + 2 < NCH32) {
            const uint2* ga = gA + (ck + 2) * 16;
            const uint2* gb = gB + (size_t)(ck + 2) * bStride;
            a0 = *(const uint4*)(ga);
            a1 = *(const uint4*)(ga + 2);
            b0 = *(const uint4*)(gb);
            b1 = *(const uint4*)(gb + 2);
        }
        mma_stage<STG>(aBase, bBase, acc);
        if (ck + 2 < NCH32) {
            sts128(sAfill,      a0.x, a0.y, a0.z, a0.w);
            sts128(sAfill + 16, a1.x, a1.y, a1.z, a1.w);
            sts128(sBfill,      b0.x, b0.y, b0.z, b0.w);
            sts128(sBfill + 16, b1.x, b1.y, b1.z, b1.w);
        }
        __syncthreads();
    }

    // ---------------- epilogue (verified logic) ----------------
    const int mrow = mBlock + warpM * 32 + g;
    const int ncol = nBlock + warpN * 32 + t * 2;

    #pragma unroll
    for (int mf = 0; mf < 2; mf++) {
        const int m = mrow + mf * 16;
        #pragma unroll
        for (int nf = 0; nf < 4; nf++) {
            const int n = ncol + nf * 8;
            float* c = acc[mf][nf];
            if (MODE == 0) {
                *(float2*)(Cout + (size_t)m * N + n)       = make_float2(c[0], c[1]);
                *(float2*)(Cout + (size_t)(m + 8) * N + n) = make_float2(c[2], c[3]);
            } else {
                const int sec = n >> 10;            // 0=q 1=k 2=v
                const int c0i = n & (CH - 1);
                const int h   = c0i >> 6;
                const int d   = c0i & 63;           // even
                const int bIdx = m >> 11;
                const int s    = m & (SEQ - 1);
                const size_t bh = (size_t)(bIdx * HEADS + h);
                if (sec == 2) {
                    const float v0 = vb[c0i], v1 = vb[c0i + 1];
                    float* dst = g_V + (bh * SEQ + (size_t)s) * HDIM + d;
                    *(float2*)dst = make_float2(c[0] + v0, c[1] + v1);
                    *(float2*)(dst + 8 * HDIM) = make_float2(c[2] + v0, c[3] + v1);
                } else {
                    float v0 = c[0], v1 = c[1], v2 = c[2], v3 = c[3];
                    if (sec == 0) {
                        const float q0 = qb[c0i], q1 = qb[c0i + 1];
                        v0 += q0; v1 += q1; v2 += q0; v3 += q1;
                    }
                    const int p = d >> 1;
                    const float sn0 = g_sin[s * HALF + p],       cs0 = g_cos[s * HALF + p];
                    const float sn8 = g_sin[(s + 8) * HALF + p], cs8 = g_cos[(s + 8) * HALF + p];
                    float o0 = v0 * cs0 - v1 * sn0;
                    float o1 = v1 * cs0 + v0 * sn0;
                    float o2 = v2 * cs8 - v3 * sn8;
                    float o3 = v3 * cs8 + v2 * sn8;
                    if (sec == 0) { o0 *= 0.125f; o1 *= 0.125f; o2 *= 0.125f; o3 *= 0.125f; }
                    uint32_t hi0, lo0, hi1, lo1;
                    cvt_pair(o0, o1, hi0, lo0);      // row s
                    cvt_pair(o2, o3, hi1, lo1);      // row s+8
                    const int d2 = d >> 1;
                    if (sec == 0) {
                        uint2* qp = g_Qe + ((bh * SEQ + (size_t)s) * 32 + d2);
                        *qp            = make_uint2(hi0, lo0);
                        *(qp + 8 * 32) = make_uint2(hi1, lo1);
                    } else {
                        uint2* kp = g_Ke + ((bh * 32 + (size_t)d2) * SEQ + s);
                        *kp       = make_uint2(hi0, lo0);
                        *(kp + 8) = make_uint2(hi1, lo1);
                    }
                }
            }
        }
    }
}

// ---------------------------------------------------------------------------
// MMA flash attention v2 (round-16 verified): 128x64 tiles, 8 warps, causal.
// Finalize now writes g_AOe (split entries) directly for the out-projection.
// ---------------------------------------------------------------------------
#define FAR 288
#define FBR 544
#define FSMV (32*FBR)
#define FSMT (128*FAR)

__global__ __launch_bounds__(256)
void flash_mma_kernel()
{
    __shared__ __align__(16) char sm[FSMT];
    const uint32_t smb = smem_to_u32(sm);
    const int tid = threadIdx.x;
    const int lane = tid & 31;
    const int wm = tid >> 5;
    const int g = lane >> 2;
    const int t = lane & 3;
    const int bh = blockIdx.y;
    const int qt = (gridDim.x - 1) - blockIdx.x;
    const int q0 = qt * 128;
    const int ktmax = 2 * qt + 1;

    {
        const int row = tid >> 1;
        const int half = tid & 1;
        const uint4* src = (const uint4*)(g_Qe
            + ((size_t)(bh * SEQ + q0 + row) * 32 + half * 16));
        const uint32_t dst = smb + (uint32_t)(row * FAR + half * 128);
        #pragma unroll
        for (int i = 0; i < 8; i++) {
            uint4 v = src[i];
            sts128(dst + i * 16, v.x, v.y, v.z, v.w);
        }
    }
    __syncthreads();

    uint2 aq[4][4];
    {
        const uint32_t abase = smb + (uint32_t)((wm * 16 + g) * FAR + t * 8);
        #pragma unroll
        for (int ks = 0; ks < 4; ks++) {
            aq[ks][0] = lds64(abase + ks * 64);
            aq[ks][1] = lds64(abase + ks * 64 + 8 * FAR);
            aq[ks][2] = lds64(abase + ks * 64 + 32);
            aq[ks][3] = lds64(abase + ks * 64 + 8 * FAR + 32);
        }
    }

    float oacc[8][4];
    #pragma unroll
    for (int nf = 0; nf < 8; nf++)
        #pragma unroll
        for (int j = 0; j < 4; j++) oacc[nf][j] = 0.0f;
    float m0 = -1e30f, m1 = -1e30f, lsum0 = 0.0f, lsum1 = 0.0f;

    for (int kt = 0; kt <= ktmax; kt++) {
        const int k0 = kt * 64;
        __syncthreads();

        {
            const int d2 = tid >> 3, seg = tid & 7;
            const uint4* src = (const uint4*)(g_Ke
                + ((size_t)(bh * 32 + d2) * SEQ + k0 + seg * 8));
            const uint32_t dst = smb + (uint32_t)(d2 * FBR + seg * 64);
            #pragma unroll
            for (int i = 0; i < 4; i++) {
                uint4 v = src[i];
                sts128(dst + i * 16, v.x, v.y, v.z, v.w);
            }
        }
        {
            const int s2 = tid >> 3, seg = tid & 7;
            const float* ra = g_V + ((size_t)bh * SEQ + k0 + 2 * s2) * HDIM + seg * 8;
            const float* rb = ra + HDIM;
            const uint32_t dst = smb + FSMV + (uint32_t)(s2 * FBR + seg * 64);
            #pragma unroll
            for (int i = 0; i < 2; i++) {
                float4 va = *(const float4*)(ra + 4 * i);
                float4 vb = *(const float4*)(rb + 4 * i);
                uint32_t h0, l0, h1, l1;
                cvt_pair(va.x, vb.x, h0, l0); cvt_pair(va.y, vb.y, h1, l1);
                sts128(dst + i * 32, h0, l0, h1, l1);
                cvt_pair(va.z, vb.z, h0, l0); cvt_pair(va.w, vb.w, h1, l1);
                sts128(dst + i * 32 + 16, h0, l0, h1, l1);
            }
        }
        __syncthreads();

        if (kt == ktmax && wm < 4) continue;

        float sacc[8][4];
        #pragma unroll
        for (int nf = 0; nf < 8; nf++)
            #pragma unroll
            for (int j = 0; j < 4; j++) sacc[nf][j] = 0.0f;

        const uint32_t kb = smb + (uint32_t)(t * FBR + g * 8);
        #pragma unroll
        for (int nf = 0; nf < 8; nf++) {
            #pragma unroll
            for (int ks = 0; ks < 4; ks++) {
                uint2 b0 = lds64(kb + ks * 8 * FBR + nf * 64);
                uint2 b1 = lds64(kb + ks * 8 * FBR + 4 * FBR + nf * 64);
                MMA_F16(sacc[nf], aq[ks][0].x, aq[ks][1].x, aq[ks][2].x, aq[ks][3].x, b0.x, b1.x);
                MMA_F16(sacc[nf], aq[ks][0].x, aq[ks][1].x, aq[ks][2].x, aq[ks][3].x, b0.y, b1.y);
                MMA_F16(sacc[nf], aq[ks][0].y, aq[ks][1].y, aq[ks][2].y, aq[ks][3].y, b0.x, b1.x);
            }
        }

        if (kt >= ktmax - 1) {
            const int koff = k0 - q0;
            const int r0 = wm * 16 + g - koff;
            const int r1 = r0 + 8;
            #pragma unroll
            for (int nf = 0; nf < 8; nf++) {
                const int c = nf * 8 + 2 * t;
                if (c > r0)     sacc[nf][0] = -1e30f;
                if (c + 1 > r0) sacc[nf][1] = -1e30f;
                if (c > r1)     sacc[nf][2] = -1e30f;
                if (c + 1 > r1) sacc[nf][3] = -1e30f;
            }
        }

        float mx0 = -1e30f, mx1 = -1e30f;
        #pragma unroll
        for (int nf = 0; nf < 8; nf++) {
            mx0 = fmaxf(mx0, fmaxf(sacc[nf][0], sacc[nf][1]));
            mx1 = fmaxf(mx1, fmaxf(sacc[nf][2], sacc[nf][3]));
        }
        #pragma unroll
        for (int ofs = 1; ofs < 4; ofs <<= 1) {
            mx0 = fmaxf(mx0, __shfl_xor_sync(0xffffffffu, mx0, ofs));
            mx1 = fmaxf(mx1, __shfl_xor_sync(0xffffffffu, mx1, ofs));
        }
        const float mn0 = fmaxf(m0, mx0);
        const float mn1 = fmaxf(m1, mx1);
        const float al0 = __expf(m0 - mn0);
        const float al1 = __expf(m1 - mn1);
        float sum0 = 0.0f, sum1 = 0.0f;
        #pragma unroll
        for (int nf = 0; nf < 8; nf++) {
            sacc[nf][0] = __expf(sacc[nf][0] - mn0);
            sacc[nf][1] = __expf(sacc[nf][1] - mn0);
            sacc[nf][2] = __expf(sacc[nf][2] - mn1);
            sacc[nf][3] = __expf(sacc[nf][3] - mn1);
            sum0 += sacc[nf][0] + sacc[nf][1];
            sum1 += sacc[nf][2] + sacc[nf][3];
        }
        #pragma unroll
        for (int ofs = 1; ofs < 4; ofs <<= 1) {
            sum0 += __shfl_xor_sync(0xffffffffu, sum0, ofs);
            sum1 += __shfl_xor_sync(0xffffffffu, sum1, ofs);
        }
        lsum0 = lsum0 * al0 + sum0;
        lsum1 = lsum1 * al1 + sum1;
        m0 = mn0;
        m1 = mn1;
        #pragma unroll
        for (int nf = 0; nf < 8; nf++) {
            oacc[nf][0] *= al0; oacc[nf][1] *= al0;
            oacc[nf][2] *= al1; oacc[nf][3] *= al1;
        }

        uint2 pa[4][4];
        #pragma unroll
        for (int ks = 0; ks < 4; ks++) {
            cvt_pair(sacc[2*ks][0],   sacc[2*ks][1],   pa[ks][0].x, pa[ks][0].y);
            cvt_pair(sacc[2*ks][2],   sacc[2*ks][3],   pa[ks][1].x, pa[ks][1].y);
            cvt_pair(sacc[2*ks+1][0], sacc[2*ks+1][1], pa[ks][2].x, pa[ks][2].y);
            cvt_pair(sacc[2*ks+1][2], sacc[2*ks+1][3], pa[ks][3].x, pa[ks][3].y);
        }

        const uint32_t vbp = smb + FSMV + (uint32_t)(t * FBR + g * 8);
        #pragma unroll
        for (int nf = 0; nf < 8; nf++) {
            #pragma unroll
            for (int ks = 0; ks < 4; ks++) {
                uint2 b0 = lds64(vbp + ks * 8 * FBR + nf * 64);
                uint2 b1 = lds64(vbp + ks * 8 * FBR + 4 * FBR + nf * 64);
                MMA_F16(oacc[nf], pa[ks][0].x, pa[ks][1].x, pa[ks][2].x, pa[ks][3].x, b0.x, b1.x);
                MMA_F16(oacc[nf], pa[ks][0].x, pa[ks][1].x, pa[ks][2].x, pa[ks][3].x, b0.y, b1.y);
                MMA_F16(oacc[nf], pa[ks][0].y, pa[ks][1].y, pa[ks][2].y, pa[ks][3].y, b0.x, b1.x);
            }
        }
    }

    // ---- finalize: write split A-layout entries for the out-projection ----
    const float inv0 = 1.0f / lsum0;
    const float inv1 = 1.0f / lsum1;
    const int b = bh >> 4;
    const int h = bh & 15;
    const int row0 = q0 + wm * 16 + g;
    #pragma unroll
    for (int nf = 0; nf < 8; nf++) {
        const int k2col = h * 32 + nf * 4 + t;
        uint32_t hi, lo;
        cvt_pair(oacc[nf][0] * inv0, oacc[nf][1] * inv0, hi, lo);
        g_AOe[(size_t)(b * SEQ + row0) * K2N + k2col] = make_uint2(hi, lo);
        cvt_pair(oacc[nf][2] * inv1, oacc[nf][3] * inv1, hi, lo);
        g_AOe[(size_t)(b * SEQ + row0 + 8) * K2N + k2col] = make_uint2(hi, lo);
    }
}

// ---------------------------------------------------------------------------
extern "C" void kernel_launch(void* const* d_in, const int* in_sizes, int n_in,
                              void* d_out, int out_size)
{
    const float* x      = (const float*)d_in[0];
    const float* w_qkv  = (const float*)d_in[1];
    const float* q_bias = (const float*)d_in[2];
    const float* v_bias = (const float*)d_in[3];
    const float* w_out  = (const float*)d_in[4];
    float* out = (float*)d_out;

    cudaFuncSetAttribute(gemm_f16<1>,
                         cudaFuncAttributeMaxDynamicSharedMemorySize, SMEM_TOT);
    cudaFuncSetAttribute(gemm_f16<0>,
                         cudaFuncAttributeMaxDynamicSharedMemorySize, SMEM_TOT);

    rope_table_kernel<<<SEQ * HALF / 256, 256>>>();

    // one-time operand splits
    convert_x_kernel<<<(MROWS * K2N) / 256, 256>>>(x);
    convert_w_kernel<0><<<dim3(NQKV / 256, K2N), 256>>>(w_qkv, NQKV);
    convert_w_kernel<1><<<dim3(CH / 256, K2N), 256>>>(w_out, CH);

    // QKV projection + bias/RoPE/scale -> g_Qe/g_Ke (split), g_V (f32)
    gemm_f16<1><<<dim3(NQKV / 128, MROWS / 128), NTHREADS, SMEM_TOT>>>(
        nullptr, q_bias, v_bias, NQKV);

    // causal MMA flash attention -> g_AOe (split)
    flash_mma_kernel<<<dim3(SEQ / 128, BATCH * HEADS), 256>>>();

    // output projection -> d_out
    gemm_f16<0><<<dim3(CH / 128, MROWS / 128), NTHREADS, SMEM_TOT>>>(
        out, nullptr, nullptr, CH);
}